// round 1
// baseline (speedup 1.0000x reference)
#include <cuda_runtime.h>
#include <math.h>

#define BB 16
#define HH 64
#define WW 64
#define HID 12
#define MODES 16
#define LIFTC 256
#define OUTC 640
#define NPIX (BB*HH*WW)      /* 65536 */
#define HWSZ (HH*WW)         /* 4096 */
#define EPS 1e-5f

// ---------------- scratch (device globals; no allocations allowed) ----------
__device__ __align__(16) float g_twc[64];
__device__ __align__(16) float g_tws[64];
__device__ float g_scale, g_shift;
__device__ float g_branch[BB];
__device__ __align__(16) float g_t0[BB*HID*HWSZ];   // 3 MB ping
__device__ __align__(16) float g_t1[BB*HID*HWSZ];   // 3 MB pong
__device__ __align__(16) float2 g_xcol[BB*HID*HH*MODES];  // [bc][h][k]
__device__ __align__(16) float2 g_xft [BB*HID*32*MODES];  // [bc][mi][k]
__device__ __align__(16) float2 g_yft [BB*HID*32*MODES];  // [bo][mi][k]
__device__ __align__(16) float2 g_Y   [BB*HID*HH*MODES];  // [bo][h][k]
__device__ __align__(16) float g_q[LIFTC*NPIX];           // 64 MB, [j][p]

__device__ __forceinline__ float gelu_exact(float x) { return x * normcdff(x); }

// ---------------- init twiddles --------------------------------------------
__global__ void k_init_tw() {
    int j = threadIdx.x;
    if (j < 64) {
        float s, c;
        sincospif((float)j / 32.0f, &s, &c);   // angle 2*pi*j/64
        g_twc[j] = c; g_tws[j] = s;
    }
}

// ---------------- batchnorm2d stats over all of x ---------------------------
__global__ void k_stats(const float* __restrict__ x,
                        const float* __restrict__ g2,
                        const float* __restrict__ b2) {
    __shared__ double ssum[1024];
    __shared__ double ssq[1024];
    int tid = threadIdx.x;
    double s = 0.0, q = 0.0;
    for (int i = tid; i < NPIX; i += 1024) {
        float v = x[i];
        s += (double)v; q += (double)v * (double)v;
    }
    ssum[tid] = s; ssq[tid] = q;
    __syncthreads();
    for (int o = 512; o > 0; o >>= 1) {
        if (tid < o) { ssum[tid] += ssum[tid + o]; ssq[tid] += ssq[tid + o]; }
        __syncthreads();
    }
    if (tid == 0) {
        double m = ssum[0] / (double)NPIX;
        double var = ssq[0] / (double)NPIX - m * m;
        float rstd = rsqrtf((float)var + EPS);
        float sc = g2[0] * rstd;
        g_scale = sc;
        g_shift = b2[0] - (float)m * sc;
    }
}

// ---------------- condition BN + branch MLP ---------------------------------
__global__ void k_branch(const float* __restrict__ cond,
                         const float* __restrict__ g1, const float* __restrict__ b1,
                         const float* __restrict__ w1, const float* __restrict__ bb1,
                         const float* __restrict__ w2, const float* __restrict__ bb2,
                         const float* __restrict__ w3, const float* __restrict__ bb3) {
    __shared__ float cs[2], cb[2];
    int tid = threadIdx.x;
    if (tid < 2) {
        float m = 0.f;
        for (int b = 0; b < BB; b++) m += cond[b * 2 + tid];
        m /= (float)BB;
        float v = 0.f;
        for (int b = 0; b < BB; b++) { float d = cond[b * 2 + tid] - m; v += d * d; }
        v /= (float)BB;
        float sc = rsqrtf(v + EPS) * g1[tid];
        cs[tid] = sc;
        cb[tid] = b1[tid] - m * sc;
    }
    __syncthreads();
    if (tid < BB) {
        float c0 = cond[tid * 2 + 0] * cs[0] + cb[0];
        float c1 = cond[tid * 2 + 1] * cs[1] + cb[1];
        float h1[50], h2[50];
        for (int j = 0; j < 50; j++)
            h1[j] = tanhf(c0 * w1[j] + c1 * w1[50 + j] + bb1[j]);
        for (int j = 0; j < 50; j++) {
            float a = bb2[j];
            for (int k = 0; k < 50; k++) a = fmaf(h1[k], w2[k * 50 + j], a);
            h2[j] = tanhf(a);
        }
        float a = bb3[0];
        for (int k = 0; k < 50; k++) a = fmaf(h2[k], w3[k], a);
        g_branch[tid] = tanhf(a);
    }
}

// ---------------- lifting: per pixel 1 -> 256(gelu) -> 12 -------------------
__global__ void k_lift(const float* __restrict__ x,
                       const float* __restrict__ l1w, const float* __restrict__ l1b,
                       const float* __restrict__ l2w, const float* __restrict__ l2b) {
    __shared__ float s1w[256], s1b[256], s2w[256 * 12], s2b[12];
    int tid = threadIdx.x;
    s1w[tid] = l1w[tid];
    s1b[tid] = l1b[tid];
    for (int i = tid; i < 256 * 12; i += 256) s2w[i] = l2w[i];
    if (tid < 12) s2b[tid] = l2b[tid];
    __syncthreads();

    int p = blockIdx.x * 256 + tid;
    float s = x[p] * g_scale + g_shift;
    float acc[12];
#pragma unroll
    for (int e = 0; e < 12; e++) acc[e] = 0.f;
    for (int d = 0; d < 256; d++) {
        float u = fmaf(s, s1w[d], s1b[d]);
        float gl = gelu_exact(u);
#pragma unroll
        for (int e = 0; e < 12; e++) acc[e] = fmaf(gl, s2w[d * 12 + e], acc[e]);
    }
    int b = p >> 12, hw = p & 4095;
#pragma unroll
    for (int e = 0; e < 12; e++)
        g_t0[(b * HID + e) * HWSZ + hw] = acc[e] + s2b[e];
}

// ---------------- forward DFT along W (16 freqs) ----------------------------
__global__ void k_fftW(int in_flag) {
    const float* tin = in_flag ? g_t1 : g_t0;
    __shared__ float ts[16][64];
    __shared__ float twc[64], tws[64];
    int tid = threadIdx.x;
    int bc = blockIdx.x >> 2;
    int h0 = (blockIdx.x & 3) * 16;
    if (tid < 64) { twc[tid] = g_twc[tid]; tws[tid] = g_tws[tid]; }
    for (int i = tid; i < 1024; i += 256)
        ts[i >> 6][i & 63] = tin[bc * HWSZ + (h0 + (i >> 6)) * 64 + (i & 63)];
    __syncthreads();
    int hr = tid >> 4, k = tid & 15;
    float re = 0.f, im = 0.f;
#pragma unroll 8
    for (int w = 0; w < 64; w++) {
        int j = (w * k) & 63;
        float v = ts[hr][w];
        re = fmaf(v, twc[j], re);
        im = fmaf(-v, tws[j], im);
    }
    g_xcol[(bc * 64 + h0 + hr) * 16 + k] = make_float2(re, im);
}

// ---------------- forward DFT along H at 32 mode rows -----------------------
__global__ void k_fftH() {
    __shared__ float2 sc[64 * 16];
    __shared__ float twc[64], tws[64];
    int tid = threadIdx.x;
    int bc = blockIdx.x;
    if (tid < 64) { twc[tid] = g_twc[tid]; tws[tid] = g_tws[tid]; }
    for (int i = tid; i < 1024; i += 512) sc[i] = g_xcol[bc * 1024 + i];
    __syncthreads();
    int mi = tid >> 4, k = tid & 15;
    int m = mi + (mi >= 16 ? 32 : 0);
    float re = 0.f, im = 0.f;
#pragma unroll 8
    for (int h = 0; h < 64; h++) {
        int j = (h * m) & 63;
        float2 v = sc[h * 16 + k];
        float c = twc[j], s = tws[j];
        re += v.x * c + v.y * s;   // * e^{-i theta}
        im += v.y * c - v.x * s;
    }
    g_xft[(bc * 32 + mi) * 16 + k] = make_float2(re, im);
}

// ---------------- spectral channel mix 12 -> 12 ------------------------------
__global__ void k_spec(int lay,
                       const float* __restrict__ sw1r, const float* __restrict__ sw1i,
                       const float* __restrict__ sw2r, const float* __restrict__ sw2i) {
    int idx = blockIdx.x * 256 + threadIdx.x;   // [b][o][mi][k]
    int k = idx & 15;
    int mi = (idx >> 4) & 31;
    int bo = idx >> 9;
    int o = bo % 12, b = bo / 12;
    const float* wr = (mi < 16) ? sw1r : sw2r;
    const float* wi = (mi < 16) ? sw1i : sw2i;
    int mr = (mi < 16) ? mi : mi - 16;
    float yr = 0.f, yi = 0.f;
#pragma unroll
    for (int c = 0; c < 12; c++) {
        float2 xv = g_xft[((b * 12 + c) * 32 + mi) * 16 + k];
        int off = (((lay * 12 + c) * 12 + o) * 16 + mr) * 16 + k;
        float wre = wr[off], wim = wi[off];
        yr += xv.x * wre - xv.y * wim;
        yi += xv.x * wim + xv.y * wre;
    }
    g_yft[((b * 12 + o) * 32 + mi) * 16 + k] = make_float2(yr, yi);
}

// ---------------- inverse DFT along H ----------------------------------------
__global__ void k_ifftH() {
    __shared__ float2 sy[32 * 16];
    __shared__ float twc[64], tws[64];
    int tid = threadIdx.x;
    int bo = blockIdx.x;
    if (tid < 64) { twc[tid] = g_twc[tid]; tws[tid] = g_tws[tid]; }
    if (tid < 512) sy[tid] = g_yft[bo * 512 + tid];
    __syncthreads();
    int h = tid >> 4, k = tid & 15;
    float re = 0.f, im = 0.f;
#pragma unroll
    for (int mi = 0; mi < 32; mi++) {
        int m = mi + (mi >= 16 ? 32 : 0);
        int j = (h * m) & 63;
        float2 v = sy[mi * 16 + k];
        float c = twc[j], s = tws[j];
        re += v.x * c - v.y * s;   // * e^{+i theta}
        im += v.x * s + v.y * c;
    }
    g_Y[(bo * 64 + h) * 16 + k] = make_float2(re, im);
}

// ---------------- inverse DFT along W + skip conv + gelu --------------------
__global__ void k_ifftW_skip(int lay, int in_flag,
                             const float* __restrict__ skw_g,
                             const float* __restrict__ skb_g) {
    const float* tin = in_flag ? g_t1 : g_t0;
    float* tout = in_flag ? g_t0 : g_t1;
    __shared__ float2 sy[4][16];
    __shared__ float skw[12];
    __shared__ float skb;
    __shared__ float twc[64], tws[64];
    int tid = threadIdx.x;
    int bo = blockIdx.x >> 4;
    int h0 = (blockIdx.x & 15) * 4;
    int b = bo / 12, o = bo % 12;
    if (tid < 64) { twc[tid] = g_twc[tid]; tws[tid] = g_tws[tid]; }
    if (tid < 64) {
        int hr = tid >> 4, k = tid & 15;
        sy[hr][k] = g_Y[(bo * 64 + h0 + hr) * 16 + k];
    }
    if (tid >= 64 && tid < 76) skw[tid - 64] = skw_g[((lay * 12 + (tid - 64)) * 12) + o];
    if (tid == 76) skb = skb_g[lay * 12 + o];
    __syncthreads();

    int hr = tid >> 6, w = tid & 63;
    int h = h0 + hr;
    float v = sy[hr][0].x;    // k=0: imaginary part discarded by irfft
#pragma unroll
    for (int k = 1; k < 16; k++) {
        int j = (w * k) & 63;
        v += 2.f * (sy[hr][k].x * twc[j] - sy[hr][k].y * tws[j]);
    }
    v *= (1.0f / 4096.0f);
    float sk = skb;
#pragma unroll
    for (int c = 0; c < 12; c++)
        sk = fmaf(tin[(b * 12 + c) * HWSZ + h * 64 + w], skw[c], sk);
    float r = v + sk;
    if (lay < 3) r = gelu_exact(r);
    tout[(b * 12 + o) * HWSZ + h * 64 + w] = r;
}

// ---------------- projection pass 1: 12 -> 256 (gelu), q stored [j][p] ------
__global__ void k_proj1(const float* __restrict__ p1w, const float* __restrict__ p1b) {
    __shared__ float ts[12 * 64];
    __shared__ float w1s[12 * 256];
    __shared__ float b1s[256];
    int tid = threadIdx.x;
    int bh = blockIdx.x;
    int b = bh >> 6, h = bh & 63;
    if (tid < 256) b1s[tid] = p1b[tid];
    for (int i = tid; i < 12 * 256; i += 256) w1s[i] = p1w[i];
    for (int i = tid; i < 768; i += 256)
        ts[i] = g_t0[(b * 12 + (i >> 6)) * HWSZ + h * 64 + (i & 63)];
    __syncthreads();

    int w = tid & 63;
    int jg = tid >> 6;           // 0..3
    float tv[12];
#pragma unroll
    for (int c = 0; c < 12; c++) tv[c] = ts[c * 64 + w];
    int p = bh * 64 + w;
    for (int jj = 0; jj < 64; jj++) {
        int j = jg * 64 + jj;
        float a = b1s[j];
#pragma unroll
        for (int c = 0; c < 12; c++) a = fmaf(tv[c], w1s[c * 256 + j], a);
        g_q[j * NPIX + p] = gelu_exact(a);
    }
}

// ---------------- projection pass 2: GEMM 65536x640x256 + epilogue ----------
// C[p,e] = (sum_k q[k][p]*P2[k][e] + p2b[e]) * branch[b]; out[bh][e][w]
__global__ __launch_bounds__(256, 2)
void k_gemm(const float* __restrict__ p2w, const float* __restrict__ p2b,
            float* __restrict__ out) {
    __shared__ float As[8][128];
    __shared__ float Bs[8][128];
    int tid = threadIdx.x;
    int n0 = blockIdx.x * 128;
    int m0 = blockIdx.y * 128;
    int tm = tid & 15;        // strided micro-tile: p = m0 + tm + 16*i
    int tn = tid >> 4;        // strided: e = n0 + tn + 16*j
    float acc[8][8];
#pragma unroll
    for (int i = 0; i < 8; i++)
#pragma unroll
        for (int j = 0; j < 8; j++) acc[i][j] = 0.f;

    int lr = tid >> 5;
    int lc = (tid & 31) << 2;
    for (int k0 = 0; k0 < 256; k0 += 8) {
        *(float4*)&As[lr][lc] = *(const float4*)&g_q[(k0 + lr) * NPIX + m0 + lc];
        *(float4*)&Bs[lr][lc] = *(const float4*)&p2w[(k0 + lr) * OUTC + n0 + lc];
        __syncthreads();
#pragma unroll
        for (int kk = 0; kk < 8; kk++) {
            float af[8], bf[8];
#pragma unroll
            for (int i = 0; i < 8; i++) af[i] = As[kk][tm + 16 * i];
#pragma unroll
            for (int j = 0; j < 8; j++) bf[j] = Bs[kk][tn + 16 * j];
#pragma unroll
            for (int i = 0; i < 8; i++)
#pragma unroll
                for (int j = 0; j < 8; j++)
                    acc[i][j] = fmaf(af[i], bf[j], acc[i][j]);
        }
        __syncthreads();
    }

#pragma unroll
    for (int i = 0; i < 8; i++) {
        int p = m0 + tm + 16 * i;
        int bh = p >> 6, w = p & 63;
        float br = g_branch[p >> 12];
        long base = (long)bh * (OUTC * 64) + w;
#pragma unroll
        for (int j = 0; j < 8; j++) {
            int e = n0 + tn + 16 * j;
            out[base + (long)e * 64] = (acc[i][j] + p2b[e]) * br;
        }
    }
}

// ---------------- launch ------------------------------------------------------
extern "C" void kernel_launch(void* const* d_in, const int* in_sizes, int n_in,
                              void* d_out, int out_size) {
    const float* x     = (const float*)d_in[0];
    const float* cond  = (const float*)d_in[1];
    const float* bn2_g = (const float*)d_in[2];
    const float* bn2_b = (const float*)d_in[3];
    const float* bn1_g = (const float*)d_in[4];
    const float* bn1_b = (const float*)d_in[5];
    const float* b_w1  = (const float*)d_in[6];
    const float* b_b1  = (const float*)d_in[7];
    const float* b_w2  = (const float*)d_in[8];
    const float* b_b2  = (const float*)d_in[9];
    const float* b_w3  = (const float*)d_in[10];
    const float* b_b3  = (const float*)d_in[11];
    const float* l1_w  = (const float*)d_in[12];
    const float* l1_b  = (const float*)d_in[13];
    const float* l2_w  = (const float*)d_in[14];
    const float* l2_b  = (const float*)d_in[15];
    const float* sw1r  = (const float*)d_in[16];
    const float* sw1i  = (const float*)d_in[17];
    const float* sw2r  = (const float*)d_in[18];
    const float* sw2i  = (const float*)d_in[19];
    const float* sk_w  = (const float*)d_in[20];
    const float* sk_b  = (const float*)d_in[21];
    const float* p1_w  = (const float*)d_in[22];
    const float* p1_b  = (const float*)d_in[23];
    const float* p2_w  = (const float*)d_in[24];
    const float* p2_b  = (const float*)d_in[25];
    float* out = (float*)d_out;

    k_init_tw<<<1, 64>>>();
    k_stats<<<1, 1024>>>(x, bn2_g, bn2_b);
    k_branch<<<1, 64>>>(cond, bn1_g, bn1_b, b_w1, b_b1, b_w2, b_b2, b_w3, b_b3);
    k_lift<<<NPIX / 256, 256>>>(x, l1_w, l1_b, l2_w, l2_b);

    for (int lay = 0; lay < 4; lay++) {
        int in_flag = lay & 1;   // 0: g_t0 in, 1: g_t1 in
        k_fftW<<<BB * HID * 4, 256>>>(in_flag);
        k_fftH<<<BB * HID, 512>>>();
        k_spec<<<(BB * HID * 32 * 16) / 256, 256>>>(lay, sw1r, sw1i, sw2r, sw2i);
        k_ifftH<<<BB * HID, 1024>>>();
        k_ifftW_skip<<<BB * HID * 16, 256>>>(lay, in_flag, sk_w, sk_b);
    }

    k_proj1<<<BB * HH, 256>>>(p1_w, p1_b);

    dim3 gg(OUTC / 128, NPIX / 128);
    k_gemm<<<gg, 256>>>(p2_w, p2_b, out);
}

// round 3
// speedup vs baseline: 1.6135x; 1.6135x over previous
#include <cuda_runtime.h>
#include <math.h>
#include <stdint.h>

#define BB 16
#define HH 64
#define WW 64
#define HID 12
#define MODES 16
#define LIFTC 256
#define OUTC 640
#define NPIX (BB*HH*WW)      /* 65536 */
#define HWSZ (HH*WW)         /* 4096 */
#define EPS 1e-5f

// ---------------- scratch (device globals; no allocations allowed) ----------
__device__ __align__(16) float g_twc[64];
__device__ __align__(16) float g_tws[64];
__device__ float g_scale, g_shift;
__device__ float g_branch[BB];
__device__ __align__(16) float g_t0[BB*HID*HWSZ];   // 3 MB ping
__device__ __align__(16) float g_t1[BB*HID*HWSZ];   // 3 MB pong
__device__ __align__(16) float2 g_xcol[BB*HID*HH*MODES];  // [bc][h][k]
__device__ __align__(16) float2 g_xft [BB*HID*32*MODES];  // [bc][mi][k]
__device__ __align__(16) float2 g_yft [BB*HID*32*MODES];  // [bo][mi][k]
__device__ __align__(16) float2 g_Y   [BB*HID*HH*MODES];  // [bo][h][k]
__device__ __align__(16) float g_q[NPIX*LIFTC];           // 64 MB, [p][k], tf32-rounded
__device__ __align__(16) float g_bt[OUTC*LIFTC];          // 640 KB, [e][k], tf32-rounded

__device__ __forceinline__ float gelu_exact(float x) { return x * normcdff(x); }

__device__ __forceinline__ float to_tf32(float x) {
    uint32_t r;
    asm("cvt.rna.tf32.f32 %0, %1;" : "=r"(r) : "f"(x));
    return __uint_as_float(r);
}

// ---------------- init twiddles --------------------------------------------
__global__ void k_init_tw() {
    int j = threadIdx.x;
    if (j < 64) {
        float s, c;
        sincospif((float)j / 32.0f, &s, &c);   // angle 2*pi*j/64
        g_twc[j] = c; g_tws[j] = s;
    }
}

// ---------------- batchnorm2d stats over all of x ---------------------------
__global__ void k_stats(const float* __restrict__ x,
                        const float* __restrict__ g2,
                        const float* __restrict__ b2) {
    __shared__ double ssum[1024];
    __shared__ double ssq[1024];
    int tid = threadIdx.x;
    double s = 0.0, q = 0.0;
    for (int i = tid; i < NPIX; i += 1024) {
        float v = x[i];
        s += (double)v; q += (double)v * (double)v;
    }
    ssum[tid] = s; ssq[tid] = q;
    __syncthreads();
    for (int o = 512; o > 0; o >>= 1) {
        if (tid < o) { ssum[tid] += ssum[tid + o]; ssq[tid] += ssq[tid + o]; }
        __syncthreads();
    }
    if (tid == 0) {
        double m = ssum[0] / (double)NPIX;
        double var = ssq[0] / (double)NPIX - m * m;
        float rstd = rsqrtf((float)var + EPS);
        float sc = g2[0] * rstd;
        g_scale = sc;
        g_shift = b2[0] - (float)m * sc;
    }
}

// ---------------- condition BN + branch MLP ---------------------------------
__global__ void k_branch(const float* __restrict__ cond,
                         const float* __restrict__ g1, const float* __restrict__ b1,
                         const float* __restrict__ w1, const float* __restrict__ bb1,
                         const float* __restrict__ w2, const float* __restrict__ bb2,
                         const float* __restrict__ w3, const float* __restrict__ bb3) {
    __shared__ float cs[2], cb[2];
    int tid = threadIdx.x;
    if (tid < 2) {
        float m = 0.f;
        for (int b = 0; b < BB; b++) m += cond[b * 2 + tid];
        m /= (float)BB;
        float v = 0.f;
        for (int b = 0; b < BB; b++) { float d = cond[b * 2 + tid] - m; v += d * d; }
        v /= (float)BB;
        float sc = rsqrtf(v + EPS) * g1[tid];
        cs[tid] = sc;
        cb[tid] = b1[tid] - m * sc;
    }
    __syncthreads();
    if (tid < BB) {
        float c0 = cond[tid * 2 + 0] * cs[0] + cb[0];
        float c1 = cond[tid * 2 + 1] * cs[1] + cb[1];
        float h1[50], h2[50];
        for (int j = 0; j < 50; j++)
            h1[j] = tanhf(c0 * w1[j] + c1 * w1[50 + j] + bb1[j]);
        for (int j = 0; j < 50; j++) {
            float a = bb2[j];
            for (int k = 0; k < 50; k++) a = fmaf(h1[k], w2[k * 50 + j], a);
            h2[j] = tanhf(a);
        }
        float a = bb3[0];
        for (int k = 0; k < 50; k++) a = fmaf(h2[k], w3[k], a);
        g_branch[tid] = tanhf(a);
    }
}

// ---------------- lifting: 1 -> 256(gelu) -> 12, two threads per pixel ------
__global__ void k_lift(const float* __restrict__ x,
                       const float* __restrict__ l1w, const float* __restrict__ l1b,
                       const float* __restrict__ l2w, const float* __restrict__ l2b) {
    __shared__ float s1w[256], s1b[256], s2w[256 * 12], s2b[12];
    __shared__ float sred[128 * 13];
    int tid = threadIdx.x;
    s1w[tid] = l1w[tid];
    s1b[tid] = l1b[tid];
    for (int i = tid; i < 256 * 12; i += 256) s2w[i] = l2w[i];
    if (tid < 12) s2b[tid] = l2b[tid];
    __syncthreads();

    int px = tid & 127, half = tid >> 7;
    int p = blockIdx.x * 128 + px;
    float s = x[p] * g_scale + g_shift;
    float acc[12];
#pragma unroll
    for (int e = 0; e < 12; e++) acc[e] = 0.f;
    int d0 = half * 128;
    for (int d = d0; d < d0 + 128; d++) {
        float u = fmaf(s, s1w[d], s1b[d]);
        float gl = gelu_exact(u);
#pragma unroll
        for (int e = 0; e < 12; e++) acc[e] = fmaf(gl, s2w[d * 12 + e], acc[e]);
    }
    if (half) {
#pragma unroll
        for (int e = 0; e < 12; e++) sred[px * 13 + e] = acc[e];
    }
    __syncthreads();
    if (!half) {
        int b = p >> 12, hw = p & 4095;
#pragma unroll
        for (int e = 0; e < 12; e++)
            g_t0[(b * HID + e) * HWSZ + hw] = acc[e] + sred[px * 13 + e] + s2b[e];
    }
}

// ---------------- forward DFT along W (16 freqs) ----------------------------
__global__ void k_fftW(int in_flag) {
    const float* tin = in_flag ? g_t1 : g_t0;
    __shared__ float ts[16][64];
    __shared__ float twc[64], tws[64];
    int tid = threadIdx.x;
    int bc = blockIdx.x >> 2;
    int h0 = (blockIdx.x & 3) * 16;
    if (tid < 64) { twc[tid] = g_twc[tid]; tws[tid] = g_tws[tid]; }
    for (int i = tid; i < 1024; i += 256)
        ts[i >> 6][i & 63] = tin[bc * HWSZ + (h0 + (i >> 6)) * 64 + (i & 63)];
    __syncthreads();
    int hr = tid >> 4, k = tid & 15;
    float re = 0.f, im = 0.f;
#pragma unroll 8
    for (int w = 0; w < 64; w++) {
        int j = (w * k) & 63;
        float v = ts[hr][w];
        re = fmaf(v, twc[j], re);
        im = fmaf(-v, tws[j], im);
    }
    g_xcol[(bc * 64 + h0 + hr) * 16 + k] = make_float2(re, im);
}

// ---------------- forward DFT along H at 32 mode rows -----------------------
__global__ void k_fftH() {
    __shared__ float2 sc[64 * 16];
    __shared__ float twc[64], tws[64];
    int tid = threadIdx.x;
    int bc = blockIdx.x;
    if (tid < 64) { twc[tid] = g_twc[tid]; tws[tid] = g_tws[tid]; }
    for (int i = tid; i < 1024; i += 512) sc[i] = g_xcol[bc * 1024 + i];
    __syncthreads();
    int mi = tid >> 4, k = tid & 15;
    int m = mi + (mi >= 16 ? 32 : 0);
    float re = 0.f, im = 0.f;
#pragma unroll 8
    for (int h = 0; h < 64; h++) {
        int j = (h * m) & 63;
        float2 v = sc[h * 16 + k];
        float c = twc[j], s = tws[j];
        re += v.x * c + v.y * s;   // * e^{-i theta}
        im += v.y * c - v.x * s;
    }
    g_xft[(bc * 32 + mi) * 16 + k] = make_float2(re, im);
}

// ---------------- spectral channel mix 12 -> 12 ------------------------------
__global__ void k_spec(int lay,
                       const float* __restrict__ sw1r, const float* __restrict__ sw1i,
                       const float* __restrict__ sw2r, const float* __restrict__ sw2i) {
    int idx = blockIdx.x * 256 + threadIdx.x;   // [b][o][mi][k]
    int k = idx & 15;
    int mi = (idx >> 4) & 31;
    int bo = idx >> 9;
    int o = bo % 12, b = bo / 12;
    const float* wr = (mi < 16) ? sw1r : sw2r;
    const float* wi = (mi < 16) ? sw1i : sw2i;
    int mr = (mi < 16) ? mi : mi - 16;
    float yr = 0.f, yi = 0.f;
#pragma unroll
    for (int c = 0; c < 12; c++) {
        float2 xv = g_xft[((b * 12 + c) * 32 + mi) * 16 + k];
        int off = (((lay * 12 + c) * 12 + o) * 16 + mr) * 16 + k;
        float wre = wr[off], wim = wi[off];
        yr += xv.x * wre - xv.y * wim;
        yi += xv.x * wim + xv.y * wre;
    }
    g_yft[((b * 12 + o) * 32 + mi) * 16 + k] = make_float2(yr, yi);
}

// ---------------- inverse DFT along H ----------------------------------------
__global__ void k_ifftH() {
    __shared__ float2 sy[32 * 16];
    __shared__ float twc[64], tws[64];
    int tid = threadIdx.x;
    int bo = blockIdx.x;
    if (tid < 64) { twc[tid] = g_twc[tid]; tws[tid] = g_tws[tid]; }
    if (tid < 512) sy[tid] = g_yft[bo * 512 + tid];
    __syncthreads();
    int h = tid >> 4, k = tid & 15;
    float re = 0.f, im = 0.f;
#pragma unroll
    for (int mi = 0; mi < 32; mi++) {
        int m = mi + (mi >= 16 ? 32 : 0);
        int j = (h * m) & 63;
        float2 v = sy[mi * 16 + k];
        float c = twc[j], s = tws[j];
        re += v.x * c - v.y * s;   // * e^{+i theta}
        im += v.x * s + v.y * c;
    }
    g_Y[(bo * 64 + h) * 16 + k] = make_float2(re, im);
}

// ---------------- inverse DFT along W + skip conv + gelu --------------------
__global__ void k_ifftW_skip(int lay, int in_flag,
                             const float* __restrict__ skw_g,
                             const float* __restrict__ skb_g) {
    const float* tin = in_flag ? g_t1 : g_t0;
    float* tout = in_flag ? g_t0 : g_t1;
    __shared__ float2 sy[4][16];
    __shared__ float skw[12];
    __shared__ float skb;
    __shared__ float twc[64], tws[64];
    int tid = threadIdx.x;
    int bo = blockIdx.x >> 4;
    int h0 = (blockIdx.x & 15) * 4;
    int b = bo / 12, o = bo % 12;
    if (tid < 64) { twc[tid] = g_twc[tid]; tws[tid] = g_tws[tid]; }
    if (tid < 64) {
        int hr = tid >> 4, k = tid & 15;
        sy[hr][k] = g_Y[(bo * 64 + h0 + hr) * 16 + k];
    }
    if (tid >= 64 && tid < 76) skw[tid - 64] = skw_g[((lay * 12 + (tid - 64)) * 12) + o];
    if (tid == 76) skb = skb_g[lay * 12 + o];
    __syncthreads();

    int hr = tid >> 6, w = tid & 63;
    int h = h0 + hr;
    float v = sy[hr][0].x;    // k=0: imaginary part discarded by irfft
#pragma unroll
    for (int k = 1; k < 16; k++) {
        int j = (w * k) & 63;
        v += 2.f * (sy[hr][k].x * twc[j] - sy[hr][k].y * tws[j]);
    }
    v *= (1.0f / 4096.0f);
    float sk = skb;
#pragma unroll
    for (int c = 0; c < 12; c++)
        sk = fmaf(tin[(b * 12 + c) * HWSZ + h * 64 + w], skw[c], sk);
    float r = v + sk;
    if (lay < 3) r = gelu_exact(r);
    tout[(b * 12 + o) * HWSZ + h * 64 + w] = r;
}

// ---------------- transpose + tf32-round p2w: [256][640] -> g_bt[640][256] ---
__global__ void k_transp(const float* __restrict__ w) {
    __shared__ float t[32][33];
    int e0 = blockIdx.x * 32, k0 = blockIdx.y * 32;
    t[threadIdx.y][threadIdx.x] = w[(k0 + threadIdx.y) * OUTC + e0 + threadIdx.x];
    __syncthreads();
    g_bt[(e0 + threadIdx.y) * 256 + k0 + threadIdx.x] = to_tf32(t[threadIdx.x][threadIdx.y]);
}

// ---------------- projection pass 1: 12 -> 256 gelu, q[p][k] tf32-rounded ----
// warp per pixel: lane handles j = lid*4 + r*128, r = 0,1 (two float4 stores)
__global__ void k_proj1(const float* __restrict__ p1w, const float* __restrict__ p1b) {
    __shared__ float w1s[12 * 256];
    __shared__ float b1s[256];
    int tid = threadIdx.x;
    int wid = tid >> 5, lid = tid & 31;
    if (tid < 256) b1s[tid] = p1b[tid];
    for (int i = tid; i < 12 * 256; i += 256) w1s[i] = p1w[i];
    __syncthreads();

    int p = blockIdx.x * 8 + wid;
    int b = p >> 12, hw = p & 4095;
    float tv[12];
#pragma unroll
    for (int c = 0; c < 12; c++) tv[c] = g_t0[(b * 12 + c) * HWSZ + hw];

#pragma unroll
    for (int r = 0; r < 2; r++) {
        int jb = r * 128 + lid * 4;
        float4 v;
        float* vp = (float*)&v;
#pragma unroll
        for (int jj = 0; jj < 4; jj++) {
            int j = jb + jj;
            float a = b1s[j];
#pragma unroll
            for (int c = 0; c < 12; c++) a = fmaf(tv[c], w1s[c * 256 + j], a);
            vp[jj] = to_tf32(gelu_exact(a));
        }
        *(float4*)&g_q[(size_t)p * 256 + jb] = v;
    }
}

// ---------------- projection pass 2: mma.sync tf32 GEMM 65536x640x256 --------
// C[p,e] = (sum_k q[p][k]*Bt[e][k] + p2b[e]) * branch[b]; out[b][h][e][w]
#define PADK 36
#define STAGEF 9216   /* floats per stage: 2 * 128*36 */

__device__ __forceinline__ void mma16n8k8(float* c, const uint32_t* a, const uint32_t* b) {
    asm volatile(
        "mma.sync.aligned.m16n8k8.row.col.f32.tf32.tf32.f32 "
        "{%0,%1,%2,%3}, {%4,%5,%6,%7}, {%8,%9}, {%0,%1,%2,%3};"
        : "+f"(c[0]), "+f"(c[1]), "+f"(c[2]), "+f"(c[3])
        : "r"(a[0]), "r"(a[1]), "r"(a[2]), "r"(a[3]), "r"(b[0]), "r"(b[1]));
}

__global__ __launch_bounds__(256, 2)
void k_gemm_mma(const float* __restrict__ p2b, float* __restrict__ out) {
    extern __shared__ float sm[];
    __shared__ float sPb[128];
    int tid = threadIdx.x;
    int wid = tid >> 5, lane = tid & 31;
    int tig = lane & 3, grp = lane >> 2;
    int wm = wid & 1, wn = wid >> 1;         // warp tile: 64 rows x 32 cols
    int n0 = blockIdx.x * 128;
    int m0 = blockIdx.y * 128;
    if (tid < 128) sPb[tid] = p2b[n0 + tid];

    const float* Aop = g_q + (size_t)m0 * 256;
    const float* Bop = g_bt + (size_t)n0 * 256;

    float acc[4][4][4];
#pragma unroll
    for (int i = 0; i < 4; i++)
#pragma unroll
        for (int j = 0; j < 4; j++)
#pragma unroll
            for (int r = 0; r < 4; r++) acc[i][j][r] = 0.f;

#define PREFETCH(ch) do {                                                     \
    int st_ = (ch) & 1;                                                       \
    float* Ab_ = sm + st_ * STAGEF;                                           \
    float* Bb_ = Ab_ + 4608;                                                  \
    int k0_ = (ch) * 32;                                                      \
    _Pragma("unroll")                                                         \
    for (int it = 0; it < 4; it++) {                                          \
        int fi = tid + it * 256;                                              \
        int row = fi >> 3, c4 = (fi & 7) * 4;                                 \
        uint32_t da = (uint32_t)__cvta_generic_to_shared(Ab_ + row * PADK + c4); \
        const float* ga = Aop + (size_t)row * 256 + k0_ + c4;                 \
        asm volatile("cp.async.cg.shared.global [%0], [%1], 16;" :: "r"(da), "l"(ga)); \
        uint32_t db = (uint32_t)__cvta_generic_to_shared(Bb_ + row * PADK + c4); \
        const float* gb = Bop + (size_t)row * 256 + k0_ + c4;                 \
        asm volatile("cp.async.cg.shared.global [%0], [%1], 16;" :: "r"(db), "l"(gb)); \
    }                                                                         \
    asm volatile("cp.async.commit_group;" ::: "memory");                      \
} while (0)

    PREFETCH(0);

    for (int ch = 0; ch < 8; ch++) {
        if (ch < 7) {
            PREFETCH(ch + 1);
            asm volatile("cp.async.wait_group 1;" ::: "memory");
        } else {
            asm volatile("cp.async.wait_group 0;" ::: "memory");
        }
        __syncthreads();
        const float* Ab = sm + (ch & 1) * STAGEF;
        const float* Bb = Ab + 4608;

#pragma unroll
        for (int kk = 0; kk < 4; kk++) {
            int kb = kk * 8;
            uint32_t af[4][4], bf[4][2];
#pragma unroll
            for (int mt = 0; mt < 4; mt++) {
                int r0 = wm * 64 + mt * 16 + grp;
                af[mt][0] = __float_as_uint(Ab[r0 * PADK + kb + tig]);
                af[mt][1] = __float_as_uint(Ab[(r0 + 8) * PADK + kb + tig]);
                af[mt][2] = __float_as_uint(Ab[r0 * PADK + kb + tig + 4]);
                af[mt][3] = __float_as_uint(Ab[(r0 + 8) * PADK + kb + tig + 4]);
            }
#pragma unroll
            for (int nt = 0; nt < 4; nt++) {
                int e = wn * 32 + nt * 8 + grp;
                bf[nt][0] = __float_as_uint(Bb[e * PADK + kb + tig]);
                bf[nt][1] = __float_as_uint(Bb[e * PADK + kb + tig + 4]);
            }
#pragma unroll
            for (int mt = 0; mt < 4; mt++)
#pragma unroll
                for (int nt = 0; nt < 4; nt++)
                    mma16n8k8(acc[mt][nt], af[mt], bf[nt]);
        }
        __syncthreads();
    }

    // epilogue: (acc + bias) * branch, scattered but 32B-sector aligned
    float br = g_branch[m0 >> 12];
#pragma unroll
    for (int mt = 0; mt < 4; mt++) {
        int row0 = m0 + wm * 64 + mt * 16 + grp;
        int row1 = row0 + 8;
        float* o0 = out + (size_t)(row0 >> 6) * (OUTC * 64) + (row0 & 63);
        float* o1 = out + (size_t)(row1 >> 6) * (OUTC * 64) + (row1 & 63);
#pragma unroll
        for (int nt = 0; nt < 4; nt++) {
            int el = wn * 32 + nt * 8 + 2 * tig;     // local e in [0,128)
            int e = n0 + el;
            float b0 = sPb[el], b1 = sPb[el + 1];
            __stcs(o0 + (size_t)e * 64,       (acc[mt][nt][0] + b0) * br);
            __stcs(o0 + (size_t)(e + 1) * 64, (acc[mt][nt][1] + b1) * br);
            __stcs(o1 + (size_t)e * 64,       (acc[mt][nt][2] + b0) * br);
            __stcs(o1 + (size_t)(e + 1) * 64, (acc[mt][nt][3] + b1) * br);
        }
    }
#undef PREFETCH
}

#define GEMM_SMEM (2 * STAGEF * 4)   /* 73728 bytes */

// ---------------- launch ------------------------------------------------------
extern "C" void kernel_launch(void* const* d_in, const int* in_sizes, int n_in,
                              void* d_out, int out_size) {
    const float* x     = (const float*)d_in[0];
    const float* cond  = (const float*)d_in[1];
    const float* bn2_g = (const float*)d_in[2];
    const float* bn2_b = (const float*)d_in[3];
    const float* bn1_g = (const float*)d_in[4];
    const float* bn1_b = (const float*)d_in[5];
    const float* b_w1  = (const float*)d_in[6];
    const float* b_b1  = (const float*)d_in[7];
    const float* b_w2  = (const float*)d_in[8];
    const float* b_b2  = (const float*)d_in[9];
    const float* b_w3  = (const float*)d_in[10];
    const float* b_b3  = (const float*)d_in[11];
    const float* l1_w  = (const float*)d_in[12];
    const float* l1_b  = (const float*)d_in[13];
    const float* l2_w  = (const float*)d_in[14];
    const float* l2_b  = (const float*)d_in[15];
    const float* sw1r  = (const float*)d_in[16];
    const float* sw1i  = (const float*)d_in[17];
    const float* sw2r  = (const float*)d_in[18];
    const float* sw2i  = (const float*)d_in[19];
    const float* sk_w  = (const float*)d_in[20];
    const float* sk_b  = (const float*)d_in[21];
    const float* p1_w  = (const float*)d_in[22];
    const float* p1_b  = (const float*)d_in[23];
    const float* p2_w  = (const float*)d_in[24];
    const float* p2_b  = (const float*)d_in[25];
    float* out = (float*)d_out;

    cudaFuncSetAttribute(k_gemm_mma, cudaFuncAttributeMaxDynamicSharedMemorySize, GEMM_SMEM);

    k_init_tw<<<1, 64>>>();
    k_stats<<<1, 1024>>>(x, bn2_g, bn2_b);
    k_branch<<<1, 64>>>(cond, bn1_g, bn1_b, b_w1, b_b1, b_w2, b_b2, b_w3, b_b3);
    k_lift<<<NPIX / 128, 256>>>(x, l1_w, l1_b, l2_w, l2_b);

    dim3 tg(OUTC / 32, 256 / 32);
    k_transp<<<tg, dim3(32, 32)>>>(p2_w);

    for (int lay = 0; lay < 4; lay++) {
        int in_flag = lay & 1;   // 0: g_t0 in, 1: g_t1 in
        k_fftW<<<BB * HID * 4, 256>>>(in_flag);
        k_fftH<<<BB * HID, 512>>>();
        k_spec<<<(BB * HID * 32 * 16) / 256, 256>>>(lay, sw1r, sw1i, sw2r, sw2i);
        k_ifftH<<<BB * HID, 1024>>>();
        k_ifftW_skip<<<BB * HID * 16, 256>>>(lay, in_flag, sk_w, sk_b);
    }

    k_proj1<<<NPIX / 8, 256>>>(p1_w, p1_b);

    dim3 gg(OUTC / 128, NPIX / 128);
    k_gemm_mma<<<gg, 256, GEMM_SMEM>>>(p2_b, out);
}

// round 4
// speedup vs baseline: 1.7433x; 1.0805x over previous
#include <cuda_runtime.h>
#include <math.h>
#include <stdint.h>

#define BB 16
#define HH 64
#define WW 64
#define HID 12
#define MODES 16
#define LIFTC 256
#define OUTC 640
#define NPIX (BB*HH*WW)      /* 65536 */
#define HWSZ (HH*WW)         /* 4096 */
#define EPS 1e-5f
#define TAB_N 8192
#define TAB_LO (-9.0f)
#define TAB_STEP (18.0f / TAB_N)
#define TAB_INV (TAB_N / 18.0f)

// ---------------- scratch (device globals; no allocations allowed) ----------
__device__ __align__(16) float g_twc[64];
__device__ __align__(16) float g_tws[64];
__device__ float g_scale, g_shift;
__device__ float g_branch[BB];
__device__ __align__(16) float g_t0[BB*HID*HWSZ];   // 3 MB ping
__device__ __align__(16) float g_t1[BB*HID*HWSZ];   // 3 MB pong
__device__ __align__(16) float2 g_xft [BB*HID*32*MODES];  // [bc][mi][k]
__device__ __align__(16) float2 g_yft [BB*HID*32*MODES];  // [bo][mi][k]
__device__ __align__(16) float g_q[NPIX*LIFTC];           // 64 MB, [p][k], tf32-rounded
__device__ __align__(16) float g_bt[OUTC*LIFTC];          // 640 KB, [e][k], tf32-rounded
__device__ __align__(16) float g_tab[(TAB_N + 1) * 12];   // lifting lookup table

__device__ __forceinline__ float gelu_exact(float x) { return x * normcdff(x); }

__device__ __forceinline__ float to_tf32(float x) {
    uint32_t r;
    asm("cvt.rna.tf32.f32 %0, %1;" : "=r"(r) : "f"(x));
    return __uint_as_float(r);
}

// ---------------- init twiddles --------------------------------------------
__global__ void k_init_tw() {
    int j = threadIdx.x;
    if (j < 64) {
        float s, c;
        sincospif((float)j / 32.0f, &s, &c);   // angle 2*pi*j/64
        g_twc[j] = c; g_tws[j] = s;
    }
}

// ---------------- batchnorm2d stats over all of x ---------------------------
__global__ void k_stats(const float* __restrict__ x,
                        const float* __restrict__ g2,
                        const float* __restrict__ b2) {
    __shared__ double ssum[1024];
    __shared__ double ssq[1024];
    int tid = threadIdx.x;
    double s = 0.0, q = 0.0;
    for (int i = tid; i < NPIX; i += 1024) {
        float v = x[i];
        s += (double)v; q += (double)v * (double)v;
    }
    ssum[tid] = s; ssq[tid] = q;
    __syncthreads();
    for (int o = 512; o > 0; o >>= 1) {
        if (tid < o) { ssum[tid] += ssum[tid + o]; ssq[tid] += ssq[tid + o]; }
        __syncthreads();
    }
    if (tid == 0) {
        double m = ssum[0] / (double)NPIX;
        double var = ssq[0] / (double)NPIX - m * m;
        float rstd = rsqrtf((float)var + EPS);
        float sc = g2[0] * rstd;
        g_scale = sc;
        g_shift = b2[0] - (float)m * sc;
    }
}

// ---------------- condition BN + branch MLP ---------------------------------
__global__ void k_branch(const float* __restrict__ cond,
                         const float* __restrict__ g1, const float* __restrict__ b1,
                         const float* __restrict__ w1, const float* __restrict__ bb1,
                         const float* __restrict__ w2, const float* __restrict__ bb2,
                         const float* __restrict__ w3, const float* __restrict__ bb3) {
    __shared__ float cs[2], cb[2];
    int tid = threadIdx.x;
    if (tid < 2) {
        float m = 0.f;
        for (int b = 0; b < BB; b++) m += cond[b * 2 + tid];
        m /= (float)BB;
        float v = 0.f;
        for (int b = 0; b < BB; b++) { float d = cond[b * 2 + tid] - m; v += d * d; }
        v /= (float)BB;
        float sc = rsqrtf(v + EPS) * g1[tid];
        cs[tid] = sc;
        cb[tid] = b1[tid] - m * sc;
    }
    __syncthreads();
    if (tid < BB) {
        float c0 = cond[tid * 2 + 0] * cs[0] + cb[0];
        float c1 = cond[tid * 2 + 1] * cs[1] + cb[1];
        float h1[50], h2[50];
        for (int j = 0; j < 50; j++)
            h1[j] = tanhf(c0 * w1[j] + c1 * w1[50 + j] + bb1[j]);
        for (int j = 0; j < 50; j++) {
            float a = bb2[j];
            for (int k = 0; k < 50; k++) a = fmaf(h1[k], w2[k * 50 + j], a);
            h2[j] = tanhf(a);
        }
        float a = bb3[0];
        for (int k = 0; k < 50; k++) a = fmaf(h2[k], w3[k], a);
        g_branch[tid] = tanhf(a);
    }
}

// ---------------- build lifting lookup table --------------------------------
// tab[i][e] = sum_d l2w[d][e] * gelu(s_i * l1w[d] + l1b[d]) + l2b[e],
// s_i = TAB_LO + i*TAB_STEP
__global__ void k_tab(const float* __restrict__ l1w, const float* __restrict__ l1b,
                      const float* __restrict__ l2w, const float* __restrict__ l2b) {
    __shared__ float s1w[256], s1b[256], s2w[256 * 12], s2b[12];
    int tid = threadIdx.x;
    s1w[tid] = l1w[tid];
    s1b[tid] = l1b[tid];
    for (int i = tid; i < 256 * 12; i += 256) s2w[i] = l2w[i];
    if (tid < 12) s2b[tid] = l2b[tid];
    __syncthreads();

    int idx = blockIdx.x * 256 + tid;
    if (idx > TAB_N) return;
    float s = TAB_LO + (float)idx * TAB_STEP;
    float acc[12];
#pragma unroll
    for (int e = 0; e < 12; e++) acc[e] = s2b[e];
    for (int d = 0; d < 256; d++) {
        float u = fmaf(s, s1w[d], s1b[d]);
        float gl = gelu_exact(u);
#pragma unroll
        for (int e = 0; e < 12; e++) acc[e] = fmaf(gl, s2w[d * 12 + e], acc[e]);
    }
#pragma unroll
    for (int e = 0; e < 12; e++) g_tab[idx * 12 + e] = acc[e];
}

// ---------------- lifting via table interp ----------------------------------
__global__ void k_lift(const float* __restrict__ x) {
    int p = blockIdx.x * 256 + threadIdx.x;
    float s = x[p] * g_scale + g_shift;
    float f = (s - TAB_LO) * TAB_INV;
    f = fminf(fmaxf(f, 0.0f), (float)TAB_N - 0.0005f);
    int i0 = (int)f;
    float fr = f - (float)i0;
    const float* ta = g_tab + i0 * 12;
    int b = p >> 12, hw = p & 4095;
#pragma unroll
    for (int e = 0; e < 12; e++) {
        float a = ta[e], bb = ta[12 + e];
        g_t0[(b * HID + e) * HWSZ + hw] = fmaf(fr, bb - a, a);
    }
}

// ---------------- fused forward DFT (W then H), block per (b,c) -------------
__global__ __launch_bounds__(512)
void k_fwd(int in_flag) {
    const float* tin = in_flag ? g_t1 : g_t0;
    __shared__ float ts[4096];
    __shared__ float2 xc[64 * 16];   // [h][k]
    __shared__ float twc[64], tws[64];
    int tid = threadIdx.x;
    int bc = blockIdx.x;
    if (tid < 64) { twc[tid] = g_twc[tid]; tws[tid] = g_tws[tid]; }
#pragma unroll
    for (int i = 0; i < 2; i++)
        *(float4*)&ts[(tid + i * 512) * 4 - tid * 0 + 0] = ((void)0, *(const float4*)&tin[bc * HWSZ + (tid + i * 512) * 4]);
    __syncthreads();

    // stage 1: W-DFT -> xc[h][k], 1024 outputs, 2 per thread
#pragma unroll
    for (int r = 0; r < 2; r++) {
        int o = tid + r * 512;
        int h = o >> 4, k = o & 15;
        float re = 0.f, im = 0.f;
#pragma unroll 8
        for (int w = 0; w < 64; w++) {
            int j = (w * k) & 63;
            float v = ts[h * 64 + w];
            re = fmaf(v, twc[j], re);
            im = fmaf(-v, tws[j], im);
        }
        xc[h * 16 + k] = make_float2(re, im);
    }
    __syncthreads();

    // stage 2: H-DFT at 32 mode rows -> g_xft, 512 outputs, 1 per thread
    int mi = tid >> 4, k = tid & 15;
    int m = mi + (mi >= 16 ? 32 : 0);
    float re = 0.f, im = 0.f;
#pragma unroll 8
    for (int h = 0; h < 64; h++) {
        int j = (h * m) & 63;
        float2 v = xc[h * 16 + k];
        float c = twc[j], s = tws[j];
        re += v.x * c + v.y * s;   // * e^{-i theta}
        im += v.y * c - v.x * s;
    }
    g_xft[(bc * 32 + mi) * 16 + k] = make_float2(re, im);
}

// ---------------- spectral channel mix 12 -> 12 ------------------------------
__global__ void k_spec(int lay,
                       const float* __restrict__ sw1r, const float* __restrict__ sw1i,
                       const float* __restrict__ sw2r, const float* __restrict__ sw2i) {
    int idx = blockIdx.x * 256 + threadIdx.x;   // [b][o][mi][k]
    int k = idx & 15;
    int mi = (idx >> 4) & 31;
    int bo = idx >> 9;
    int o = bo % 12, b = bo / 12;
    const float* wr = (mi < 16) ? sw1r : sw2r;
    const float* wi = (mi < 16) ? sw1i : sw2i;
    int mr = (mi < 16) ? mi : mi - 16;
    float yr = 0.f, yi = 0.f;
#pragma unroll
    for (int c = 0; c < 12; c++) {
        float2 xv = g_xft[((b * 12 + c) * 32 + mi) * 16 + k];
        int off = (((lay * 12 + c) * 12 + o) * 16 + mr) * 16 + k;
        float wre = wr[off], wim = wi[off];
        yr += xv.x * wre - xv.y * wim;
        yi += xv.x * wim + xv.y * wre;
    }
    g_yft[((b * 12 + o) * 32 + mi) * 16 + k] = make_float2(yr, yi);
}

// ---------------- fused inverse DFT (H then W) + skip + gelu, per (b,o) -----
__global__ __launch_bounds__(512)
void k_inv(int lay, int in_flag,
           const float* __restrict__ skw_g,
           const float* __restrict__ skb_g) {
    const float* tin = in_flag ? g_t1 : g_t0;
    float* tout = in_flag ? g_t0 : g_t1;
    __shared__ float2 sy[32 * 16];
    __shared__ float2 Ys[64 * 16];
    __shared__ float twc[64], tws[64];
    __shared__ float skw[12];
    __shared__ float skb;
    int tid = threadIdx.x;
    int bo = blockIdx.x;
    int b = bo / 12, o = bo % 12;
    if (tid < 64) { twc[tid] = g_twc[tid]; tws[tid] = g_tws[tid]; }
    if (tid < 512) sy[tid] = g_yft[bo * 512 + tid];
    if (tid >= 64 && tid < 76) skw[tid - 64] = skw_g[((lay * 12 + (tid - 64)) * 12) + o];
    if (tid == 76) skb = skb_g[lay * 12 + o];
    __syncthreads();

    // stage 1: inverse H-DFT -> Ys[h][k], 1024 outputs, 2 per thread
#pragma unroll
    for (int r = 0; r < 2; r++) {
        int oo = tid + r * 512;
        int h = oo >> 4, k = oo & 15;
        float re = 0.f, im = 0.f;
#pragma unroll
        for (int mi = 0; mi < 32; mi++) {
            int m = mi + (mi >= 16 ? 32 : 0);
            int j = (h * m) & 63;
            float2 v = sy[mi * 16 + k];
            float c = twc[j], s = tws[j];
            re += v.x * c - v.y * s;   // * e^{+i theta}
            im += v.x * s + v.y * c;
        }
        Ys[h * 16 + k] = make_float2(re, im);
    }
    __syncthreads();

    // stage 2: inverse W-DFT + skip conv (+ gelu), 4096 px, 8 per thread
    int w = tid & 63, hg = tid >> 6;
#pragma unroll
    for (int i = 0; i < 8; i++) {
        int h = hg * 8 + i;
        const float2* yr = &Ys[h * 16];
        float v = yr[0].x;    // k=0: imaginary part discarded by irfft
#pragma unroll
        for (int k = 1; k < 16; k++) {
            int j = (w * k) & 63;
            v += 2.f * (yr[k].x * twc[j] - yr[k].y * tws[j]);
        }
        v *= (1.0f / 4096.0f);
        float sk = skb;
#pragma unroll
        for (int c = 0; c < 12; c++)
            sk = fmaf(tin[(b * 12 + c) * HWSZ + h * 64 + w], skw[c], sk);
        float rres = v + sk;
        if (lay < 3) rres = gelu_exact(rres);
        tout[(b * 12 + o) * HWSZ + h * 64 + w] = rres;
    }
}

// ---------------- transpose + tf32-round p2w: [256][640] -> g_bt[640][256] ---
__global__ void k_transp(const float* __restrict__ w) {
    __shared__ float t[32][33];
    int e0 = blockIdx.x * 32, k0 = blockIdx.y * 32;
    t[threadIdx.y][threadIdx.x] = w[(k0 + threadIdx.y) * OUTC + e0 + threadIdx.x];
    __syncthreads();
    g_bt[(e0 + threadIdx.y) * 256 + k0 + threadIdx.x] = to_tf32(t[threadIdx.x][threadIdx.y]);
}

// ---------------- projection pass 1: 12 -> 256 gelu, q[p][k] tf32-rounded ----
__global__ void k_proj1(const float* __restrict__ p1w, const float* __restrict__ p1b) {
    __shared__ float w1s[12 * 256];
    __shared__ float b1s[256];
    int tid = threadIdx.x;
    int wid = tid >> 5, lid = tid & 31;
    if (tid < 256) b1s[tid] = p1b[tid];
    for (int i = tid; i < 12 * 256; i += 256) w1s[i] = p1w[i];
    __syncthreads();

    int p = blockIdx.x * 8 + wid;
    int b = p >> 12, hw = p & 4095;
    float tv[12];
#pragma unroll
    for (int c = 0; c < 12; c++) tv[c] = g_t0[(b * 12 + c) * HWSZ + hw];

#pragma unroll
    for (int r = 0; r < 2; r++) {
        int jb = r * 128 + lid * 4;
        float4 v;
        float* vp = (float*)&v;
#pragma unroll
        for (int jj = 0; jj < 4; jj++) {
            int j = jb + jj;
            float a = b1s[j];
#pragma unroll
            for (int c = 0; c < 12; c++) a = fmaf(tv[c], w1s[c * 256 + j], a);
            vp[jj] = to_tf32(gelu_exact(a));
        }
        *(float4*)&g_q[(size_t)p * 256 + jb] = v;
    }
}

// ---------------- projection pass 2: mma.sync tf32 GEMM 65536x640x256 --------
#define PADK 36
#define STAGEF 9216   /* floats per stage: 2 * 128*36 */

__device__ __forceinline__ void mma16n8k8(float* c, const uint32_t* a, const uint32_t* b) {
    asm volatile(
        "mma.sync.aligned.m16n8k8.row.col.f32.tf32.tf32.f32 "
        "{%0,%1,%2,%3}, {%4,%5,%6,%7}, {%8,%9}, {%0,%1,%2,%3};"
        : "+f"(c[0]), "+f"(c[1]), "+f"(c[2]), "+f"(c[3])
        : "r"(a[0]), "r"(a[1]), "r"(a[2]), "r"(a[3]), "r"(b[0]), "r"(b[1]));
}

__global__ __launch_bounds__(256, 2)
void k_gemm_mma(const float* __restrict__ p2b, float* __restrict__ out) {
    extern __shared__ float sm[];
    __shared__ float sPb[128];
    int tid = threadIdx.x;
    int wid = tid >> 5, lane = tid & 31;
    int tig = lane & 3, grp = lane >> 2;
    int wm = wid & 1, wn = wid >> 1;         // warp tile: 64 rows x 32 cols
    int n0 = blockIdx.x * 128;
    int m0 = blockIdx.y * 128;
    if (tid < 128) sPb[tid] = p2b[n0 + tid];

    const float* Aop = g_q + (size_t)m0 * 256;
    const float* Bop = g_bt + (size_t)n0 * 256;

    float acc[4][4][4];
#pragma unroll
    for (int i = 0; i < 4; i++)
#pragma unroll
        for (int j = 0; j < 4; j++)
#pragma unroll
            for (int r = 0; r < 4; r++) acc[i][j][r] = 0.f;

#define PREFETCH(ch) do {                                                     \
    int st_ = (ch) & 1;                                                       \
    float* Ab_ = sm + st_ * STAGEF;                                           \
    float* Bb_ = Ab_ + 4608;                                                  \
    int k0_ = (ch) * 32;                                                      \
    _Pragma("unroll")                                                         \
    for (int it = 0; it < 4; it++) {                                          \
        int fi = tid + it * 256;                                              \
        int row = fi >> 3, c4 = (fi & 7) * 4;                                 \
        uint32_t da = (uint32_t)__cvta_generic_to_shared(Ab_ + row * PADK + c4); \
        const float* ga = Aop + (size_t)row * 256 + k0_ + c4;                 \
        asm volatile("cp.async.cg.shared.global [%0], [%1], 16;" :: "r"(da), "l"(ga)); \
        uint32_t db = (uint32_t)__cvta_generic_to_shared(Bb_ + row * PADK + c4); \
        const float* gb = Bop + (size_t)row * 256 + k0_ + c4;                 \
        asm volatile("cp.async.cg.shared.global [%0], [%1], 16;" :: "r"(db), "l"(gb)); \
    }                                                                         \
    asm volatile("cp.async.commit_group;" ::: "memory");                      \
} while (0)

    PREFETCH(0);

    for (int ch = 0; ch < 8; ch++) {
        if (ch < 7) {
            PREFETCH(ch + 1);
            asm volatile("cp.async.wait_group 1;" ::: "memory");
        } else {
            asm volatile("cp.async.wait_group 0;" ::: "memory");
        }
        __syncthreads();
        const float* Ab = sm + (ch & 1) * STAGEF;
        const float* Bb = Ab + 4608;

#pragma unroll
        for (int kk = 0; kk < 4; kk++) {
            int kb = kk * 8;
            uint32_t af[4][4], bf[4][2];
#pragma unroll
            for (int mt = 0; mt < 4; mt++) {
                int r0 = wm * 64 + mt * 16 + grp;
                af[mt][0] = __float_as_uint(Ab[r0 * PADK + kb + tig]);
                af[mt][1] = __float_as_uint(Ab[(r0 + 8) * PADK + kb + tig]);
                af[mt][2] = __float_as_uint(Ab[r0 * PADK + kb + tig + 4]);
                af[mt][3] = __float_as_uint(Ab[(r0 + 8) * PADK + kb + tig + 4]);
            }
#pragma unroll
            for (int nt = 0; nt < 4; nt++) {
                int e = wn * 32 + nt * 8 + grp;
                bf[nt][0] = __float_as_uint(Bb[e * PADK + kb + tig]);
                bf[nt][1] = __float_as_uint(Bb[e * PADK + kb + tig + 4]);
            }
#pragma unroll
            for (int mt = 0; mt < 4; mt++)
#pragma unroll
                for (int nt = 0; nt < 4; nt++)
                    mma16n8k8(acc[mt][nt], af[mt], bf[nt]);
        }
        __syncthreads();
    }

    // epilogue: (acc + bias) * branch, scattered but 32B-sector aligned
    float br = g_branch[m0 >> 12];
#pragma unroll
    for (int mt = 0; mt < 4; mt++) {
        int row0 = m0 + wm * 64 + mt * 16 + grp;
        int row1 = row0 + 8;
        float* o0 = out + (size_t)(row0 >> 6) * (OUTC * 64) + (row0 & 63);
        float* o1 = out + (size_t)(row1 >> 6) * (OUTC * 64) + (row1 & 63);
#pragma unroll
        for (int nt = 0; nt < 4; nt++) {
            int el = wn * 32 + nt * 8 + 2 * tig;     // local e in [0,128)
            int e = n0 + el;
            float b0 = sPb[el], b1 = sPb[el + 1];
            __stcs(o0 + (size_t)e * 64,       (acc[mt][nt][0] + b0) * br);
            __stcs(o0 + (size_t)(e + 1) * 64, (acc[mt][nt][1] + b1) * br);
            __stcs(o1 + (size_t)e * 64,       (acc[mt][nt][2] + b0) * br);
            __stcs(o1 + (size_t)(e + 1) * 64, (acc[mt][nt][3] + b1) * br);
        }
    }
#undef PREFETCH
}

#define GEMM_SMEM (2 * STAGEF * 4)   /* 73728 bytes */

// ---------------- launch ------------------------------------------------------
extern "C" void kernel_launch(void* const* d_in, const int* in_sizes, int n_in,
                              void* d_out, int out_size) {
    const float* x     = (const float*)d_in[0];
    const float* cond  = (const float*)d_in[1];
    const float* bn2_g = (const float*)d_in[2];
    const float* bn2_b = (const float*)d_in[3];
    const float* bn1_g = (const float*)d_in[4];
    const float* bn1_b = (const float*)d_in[5];
    const float* b_w1  = (const float*)d_in[6];
    const float* b_b1  = (const float*)d_in[7];
    const float* b_w2  = (const float*)d_in[8];
    const float* b_b2  = (const float*)d_in[9];
    const float* b_w3  = (const float*)d_in[10];
    const float* b_b3  = (const float*)d_in[11];
    const float* l1_w  = (const float*)d_in[12];
    const float* l1_b  = (const float*)d_in[13];
    const float* l2_w  = (const float*)d_in[14];
    const float* l2_b  = (const float*)d_in[15];
    const float* sw1r  = (const float*)d_in[16];
    const float* sw1i  = (const float*)d_in[17];
    const float* sw2r  = (const float*)d_in[18];
    const float* sw2i  = (const float*)d_in[19];
    const float* sk_w  = (const float*)d_in[20];
    const float* sk_b  = (const float*)d_in[21];
    const float* p1_w  = (const float*)d_in[22];
    const float* p1_b  = (const float*)d_in[23];
    const float* p2_w  = (const float*)d_in[24];
    const float* p2_b  = (const float*)d_in[25];
    float* out = (float*)d_out;

    cudaFuncSetAttribute(k_gemm_mma, cudaFuncAttributeMaxDynamicSharedMemorySize, GEMM_SMEM);

    k_init_tw<<<1, 64>>>();
    k_stats<<<1, 1024>>>(x, bn2_g, bn2_b);
    k_branch<<<1, 64>>>(cond, bn1_g, bn1_b, b_w1, b_b1, b_w2, b_b2, b_w3, b_b3);
    k_tab<<<(TAB_N + 1 + 255) / 256, 256>>>(l1_w, l1_b, l2_w, l2_b);
    k_lift<<<NPIX / 256, 256>>>(x);

    dim3 tg(OUTC / 32, 256 / 32);
    k_transp<<<tg, dim3(32, 32)>>>(p2_w);

    for (int lay = 0; lay < 4; lay++) {
        int in_flag = lay & 1;   // 0: g_t0 in, 1: g_t1 in
        k_fwd<<<BB * HID, 512>>>(in_flag);
        k_spec<<<(BB * HID * 32 * 16) / 256, 256>>>(lay, sw1r, sw1i, sw2r, sw2i);
        k_inv<<<BB * HID, 512>>>(lay, in_flag, sk_w, sk_b);
    }

    k_proj1<<<NPIX / 8, 256>>>(p1_w, p1_b);

    dim3 gg(OUTC / 128, NPIX / 128);
    k_gemm_mma<<<gg, 256, GEMM_SMEM>>>(p2_b, out);
}

// round 5
// speedup vs baseline: 2.0170x; 1.1570x over previous
#include <cuda_runtime.h>
#include <math.h>
#include <stdint.h>

#define BB 16
#define HH 64
#define WW 64
#define HID 12
#define MODES 16
#define LIFTC 256
#define OUTC 640
#define NPIX (BB*HH*WW)      /* 65536 */
#define HWSZ (HH*WW)         /* 4096 */
#define EPS 1e-5f
#define TAB_N 8192
#define TAB_LO (-9.0f)
#define TAB_STEP (18.0f / TAB_N)
#define TAB_INV (TAB_N / 18.0f)
#define GT_N 8192            /* gelu table: [-8, 8], step 1/512 */

// ---------------- scratch (device globals; no allocations allowed) ----------
__device__ __align__(16) float g_twc[64];
__device__ __align__(16) float g_tws[64];
__device__ float g_scale, g_shift;
__device__ float g_branch[BB];
__device__ __align__(16) float g_t0[BB*HID*HWSZ];   // 3 MB ping
__device__ __align__(16) float g_t1[BB*HID*HWSZ];   // 3 MB pong
__device__ __align__(16) float2 g_xft [BB*HID*32*MODES];  // [bc][mi][k]
__device__ __align__(16) float2 g_yft [BB*HID*32*MODES];  // [bo][mi][k]
__device__ __align__(16) float g_q[NPIX*LIFTC];           // 64 MB, [p][k], tf32-rounded
__device__ __align__(16) float g_bt[OUTC*LIFTC];          // 640 KB, [e][k], tf32-rounded
__device__ __align__(16) float g_tab[(TAB_N + 1) * 12];   // lifting lookup table
__device__ __align__(16) float g_gt[GT_N + 1];            // gelu lookup table

__device__ __forceinline__ float gelu_exact(float x) { return x * normcdff(x); }

// table gelu: linear interp on [-8,8], exact tails
__device__ __forceinline__ float gelu_tab(float a) {
    float f = fmaf(a, 512.0f, 4096.0f);
    f = fminf(fmaxf(f, 0.0f), 8191.999f);
    int i = (int)f;
    float fr = f - (float)i;
    float a0 = g_gt[i], a1 = g_gt[i + 1];
    float g = fmaf(fr, a1 - a0, a0);
    return (a >= 8.0f) ? a : g;
}

__device__ __forceinline__ float to_tf32(float x) {
    uint32_t r;
    asm("cvt.rna.tf32.f32 %0, %1;" : "=r"(r) : "f"(x));
    return __uint_as_float(r);
}

// ---------------- init twiddles --------------------------------------------
__global__ void k_init_tw() {
    int j = threadIdx.x;
    if (j < 64) {
        float s, c;
        sincospif((float)j / 32.0f, &s, &c);   // angle 2*pi*j/64
        g_twc[j] = c; g_tws[j] = s;
    }
}

// ---------------- build gelu table ------------------------------------------
__global__ void k_gtab() {
    int idx = blockIdx.x * 256 + threadIdx.x;
    if (idx <= GT_N) {
        float x = -8.0f + (float)idx * (16.0f / GT_N);
        g_gt[idx] = gelu_exact(x);
    }
}

// ---------------- batchnorm2d stats over all of x ---------------------------
__global__ void k_stats(const float* __restrict__ x,
                        const float* __restrict__ g2,
                        const float* __restrict__ b2) {
    __shared__ double ssum[1024];
    __shared__ double ssq[1024];
    int tid = threadIdx.x;
    double s = 0.0, q = 0.0;
    for (int i = tid; i < NPIX; i += 1024) {
        float v = x[i];
        s += (double)v; q += (double)v * (double)v;
    }
    ssum[tid] = s; ssq[tid] = q;
    __syncthreads();
    for (int o = 512; o > 0; o >>= 1) {
        if (tid < o) { ssum[tid] += ssum[tid + o]; ssq[tid] += ssq[tid + o]; }
        __syncthreads();
    }
    if (tid == 0) {
        double m = ssum[0] / (double)NPIX;
        double var = ssq[0] / (double)NPIX - m * m;
        float rstd = rsqrtf((float)var + EPS);
        float sc = g2[0] * rstd;
        g_scale = sc;
        g_shift = b2[0] - (float)m * sc;
    }
}

// ---------------- condition BN + branch MLP ---------------------------------
__global__ void k_branch(const float* __restrict__ cond,
                         const float* __restrict__ g1, const float* __restrict__ b1,
                         const float* __restrict__ w1, const float* __restrict__ bb1,
                         const float* __restrict__ w2, const float* __restrict__ bb2,
                         const float* __restrict__ w3, const float* __restrict__ bb3) {
    __shared__ float cs[2], cb[2];
    int tid = threadIdx.x;
    if (tid < 2) {
        float m = 0.f;
        for (int b = 0; b < BB; b++) m += cond[b * 2 + tid];
        m /= (float)BB;
        float v = 0.f;
        for (int b = 0; b < BB; b++) { float d = cond[b * 2 + tid] - m; v += d * d; }
        v /= (float)BB;
        float sc = rsqrtf(v + EPS) * g1[tid];
        cs[tid] = sc;
        cb[tid] = b1[tid] - m * sc;
    }
    __syncthreads();
    if (tid < BB) {
        float c0 = cond[tid * 2 + 0] * cs[0] + cb[0];
        float c1 = cond[tid * 2 + 1] * cs[1] + cb[1];
        float h1[50], h2[50];
        for (int j = 0; j < 50; j++)
            h1[j] = tanhf(c0 * w1[j] + c1 * w1[50 + j] + bb1[j]);
        for (int j = 0; j < 50; j++) {
            float a = bb2[j];
            for (int k = 0; k < 50; k++) a = fmaf(h1[k], w2[k * 50 + j], a);
            h2[j] = tanhf(a);
        }
        float a = bb3[0];
        for (int k = 0; k < 50; k++) a = fmaf(h2[k], w3[k], a);
        g_branch[tid] = tanhf(a);
    }
}

// ---------------- build lifting lookup table (d-parallel) --------------------
// tab[i][e] = sum_d l2w[d][e] * gelu(s_i * l1w[d] + l1b[d]) + l2b[e]
// block: 64 points x 4 d-quarters
__global__ void k_tab(const float* __restrict__ l1w, const float* __restrict__ l1b,
                      const float* __restrict__ l2w, const float* __restrict__ l2b) {
    __shared__ float s1w[256], s1b[256], s2w[256 * 12], s2b[12];
    __shared__ float red[3][64][12];
    int tid = threadIdx.x;
    s1w[tid] = l1w[tid];
    s1b[tid] = l1b[tid];
    for (int i = tid; i < 256 * 12; i += 256) s2w[i] = l2w[i];
    if (tid < 12) s2b[tid] = l2b[tid];
    __syncthreads();

    int pl = tid & 63, qd = tid >> 6;
    int pt = blockIdx.x * 64 + pl;
    float s = TAB_LO + (float)pt * TAB_STEP;
    float acc[12];
#pragma unroll
    for (int e = 0; e < 12; e++) acc[e] = 0.f;
    int d0 = qd * 64;
    for (int d = d0; d < d0 + 64; d++) {
        float u = fmaf(s, s1w[d], s1b[d]);
        float gl = gelu_exact(u);
#pragma unroll
        for (int e = 0; e < 12; e++) acc[e] = fmaf(gl, s2w[d * 12 + e], acc[e]);
    }
    if (qd > 0) {
#pragma unroll
        for (int e = 0; e < 12; e++) red[qd - 1][pl][e] = acc[e];
    }
    __syncthreads();
    if (qd == 0 && pt <= TAB_N) {
#pragma unroll
        for (int e = 0; e < 12; e++)
            g_tab[pt * 12 + e] = acc[e] + red[0][pl][e] + red[1][pl][e] + red[2][pl][e] + s2b[e];
    }
}

// ---------------- lifting via table interp ----------------------------------
__global__ void k_lift(const float* __restrict__ x) {
    int p = blockIdx.x * 256 + threadIdx.x;
    float s = x[p] * g_scale + g_shift;
    float f = (s - TAB_LO) * TAB_INV;
    f = fminf(fmaxf(f, 0.0f), (float)TAB_N - 0.0005f);
    int i0 = (int)f;
    float fr = f - (float)i0;
    const float* ta = g_tab + i0 * 12;
    int b = p >> 12, hw = p & 4095;
#pragma unroll
    for (int e = 0; e < 12; e++) {
        float a = ta[e], bb = ta[12 + e];
        g_t0[(b * HID + e) * HWSZ + hw] = fmaf(fr, bb - a, a);
    }
}

// ---------------- fused forward DFT (W then H), block per (b,c) -------------
__global__ __launch_bounds__(512)
void k_fwd(int in_flag) {
    const float* tin = in_flag ? g_t1 : g_t0;
    __shared__ float ts[4096];
    __shared__ float2 xc[64 * 16];   // [h][k]
    __shared__ float twc[64], tws[64];
    int tid = threadIdx.x;
    int bc = blockIdx.x;
    if (tid < 64) { twc[tid] = g_twc[tid]; tws[tid] = g_tws[tid]; }
#pragma unroll
    for (int i = 0; i < 2; i++)
        *(float4*)&ts[(tid + i * 512) * 4] = *(const float4*)&tin[bc * HWSZ + (tid + i * 512) * 4];
    __syncthreads();

    // stage 1: W-DFT -> xc[h][k], 1024 outputs, 2 per thread
#pragma unroll
    for (int r = 0; r < 2; r++) {
        int o = tid + r * 512;
        int h = o >> 4, k = o & 15;
        float re = 0.f, im = 0.f;
#pragma unroll 8
        for (int w = 0; w < 64; w++) {
            int j = (w * k) & 63;
            float v = ts[h * 64 + w];
            re = fmaf(v, twc[j], re);
            im = fmaf(-v, tws[j], im);
        }
        xc[h * 16 + k] = make_float2(re, im);
    }
    __syncthreads();

    // stage 2: H-DFT at 32 mode rows -> g_xft, 512 outputs, 1 per thread
    int mi = tid >> 4, k = tid & 15;
    int m = mi + (mi >= 16 ? 32 : 0);
    float re = 0.f, im = 0.f;
#pragma unroll 8
    for (int h = 0; h < 64; h++) {
        int j = (h * m) & 63;
        float2 v = xc[h * 16 + k];
        float c = twc[j], s = tws[j];
        re += v.x * c + v.y * s;   // * e^{-i theta}
        im += v.y * c - v.x * s;
    }
    g_xft[(bc * 32 + mi) * 16 + k] = make_float2(re, im);
}

// ---------------- spectral channel mix 12 -> 12 ------------------------------
__global__ void k_spec(int lay,
                       const float* __restrict__ sw1r, const float* __restrict__ sw1i,
                       const float* __restrict__ sw2r, const float* __restrict__ sw2i) {
    int idx = blockIdx.x * 256 + threadIdx.x;   // [b][o][mi][k]
    int k = idx & 15;
    int mi = (idx >> 4) & 31;
    int bo = idx >> 9;
    int o = bo % 12, b = bo / 12;
    const float* wr = (mi < 16) ? sw1r : sw2r;
    const float* wi = (mi < 16) ? sw1i : sw2i;
    int mr = (mi < 16) ? mi : mi - 16;
    float yr = 0.f, yi = 0.f;
#pragma unroll
    for (int c = 0; c < 12; c++) {
        float2 xv = g_xft[((b * 12 + c) * 32 + mi) * 16 + k];
        int off = (((lay * 12 + c) * 12 + o) * 16 + mr) * 16 + k;
        float wre = wr[off], wim = wi[off];
        yr += xv.x * wre - xv.y * wim;
        yi += xv.x * wim + xv.y * wre;
    }
    g_yft[((b * 12 + o) * 32 + mi) * 16 + k] = make_float2(yr, yi);
}

// ---------------- fused inverse DFT (H then W) + skip + gelu, per (b,o) -----
__global__ __launch_bounds__(512)
void k_inv(int lay, int in_flag,
           const float* __restrict__ skw_g,
           const float* __restrict__ skb_g) {
    const float* tin = in_flag ? g_t1 : g_t0;
    float* tout = in_flag ? g_t0 : g_t1;
    __shared__ float2 sy[32 * 16];
    __shared__ float2 Ys[64 * 16];
    __shared__ float twc[64], tws[64];
    __shared__ float skw[12];
    __shared__ float skb;
    int tid = threadIdx.x;
    int bo = blockIdx.x;
    int b = bo / 12, o = bo % 12;
    if (tid < 64) { twc[tid] = g_twc[tid]; tws[tid] = g_tws[tid]; }
    if (tid < 512) sy[tid] = g_yft[bo * 512 + tid];
    if (tid >= 64 && tid < 76) skw[tid - 64] = skw_g[((lay * 12 + (tid - 64)) * 12) + o];
    if (tid == 76) skb = skb_g[lay * 12 + o];
    __syncthreads();

    // stage 1: inverse H-DFT -> Ys[h][k], 1024 outputs, 2 per thread
#pragma unroll
    for (int r = 0; r < 2; r++) {
        int oo = tid + r * 512;
        int h = oo >> 4, k = oo & 15;
        float re = 0.f, im = 0.f;
#pragma unroll
        for (int mi = 0; mi < 32; mi++) {
            int m = mi + (mi >= 16 ? 32 : 0);
            int j = (h * m) & 63;
            float2 v = sy[mi * 16 + k];
            float c = twc[j], s = tws[j];
            re += v.x * c - v.y * s;   // * e^{+i theta}
            im += v.x * s + v.y * c;
        }
        Ys[h * 16 + k] = make_float2(re, im);
    }
    __syncthreads();

    // stage 2: inverse W-DFT + skip conv (+ gelu), 4096 px, 8 per thread
    int w = tid & 63, hg = tid >> 6;
#pragma unroll
    for (int i = 0; i < 8; i++) {
        int h = hg * 8 + i;
        const float2* yr = &Ys[h * 16];
        float v = yr[0].x;    // k=0: imaginary part discarded by irfft
#pragma unroll
        for (int k = 1; k < 16; k++) {
            int j = (w * k) & 63;
            v += 2.f * (yr[k].x * twc[j] - yr[k].y * tws[j]);
        }
        v *= (1.0f / 4096.0f);
        float sk = skb;
#pragma unroll
        for (int c = 0; c < 12; c++)
            sk = fmaf(tin[(b * 12 + c) * HWSZ + h * 64 + w], skw[c], sk);
        float rres = v + sk;
        if (lay < 3) rres = gelu_tab(rres);
        tout[(b * 12 + o) * HWSZ + h * 64 + w] = rres;
    }
}

// ---------------- transpose + tf32-round p2w: [256][640] -> g_bt[640][256] ---
__global__ void k_transp(const float* __restrict__ w) {
    __shared__ float t[32][33];
    int e0 = blockIdx.x * 32, k0 = blockIdx.y * 32;
    t[threadIdx.y][threadIdx.x] = w[(k0 + threadIdx.y) * OUTC + e0 + threadIdx.x];
    __syncthreads();
    g_bt[(e0 + threadIdx.y) * 256 + k0 + threadIdx.x] = to_tf32(t[threadIdx.x][threadIdx.y]);
}

// ---------------- projection pass 1: 12 -> 256 gelu, q[p][k] tf32-rounded ----
__global__ void k_proj1(const float* __restrict__ p1w, const float* __restrict__ p1b) {
    __shared__ float w1s[12 * 256];
    __shared__ float b1s[256];
    int tid = threadIdx.x;
    int wid = tid >> 5, lid = tid & 31;
    if (tid < 256) b1s[tid] = p1b[tid];
    for (int i = tid; i < 12 * 256; i += 256) w1s[i] = p1w[i];
    __syncthreads();

    int p = blockIdx.x * 8 + wid;
    int b = p >> 12, hw = p & 4095;
    float tv[12];
#pragma unroll
    for (int c = 0; c < 12; c++) tv[c] = g_t0[(b * 12 + c) * HWSZ + hw];

#pragma unroll
    for (int r = 0; r < 2; r++) {
        int jb = r * 128 + lid * 4;
        float4 v;
        float* vp = (float*)&v;
#pragma unroll
        for (int jj = 0; jj < 4; jj++) {
            int j = jb + jj;
            float a = b1s[j];
#pragma unroll
            for (int c = 0; c < 12; c++) a = fmaf(tv[c], w1s[c * 256 + j], a);
            vp[jj] = to_tf32(gelu_tab(a));
        }
        *(float4*)&g_q[(size_t)p * 256 + jb] = v;
    }
}

// ---------------- projection pass 2: mma.sync tf32 GEMM 65536x640x256 --------
#define PADK 36
#define STAGEF 9216   /* floats per stage: 2 * 128*36 */
#define NSTAGE 3

__device__ __forceinline__ void mma16n8k8(float* c, const uint32_t* a, const uint32_t* b) {
    asm volatile(
        "mma.sync.aligned.m16n8k8.row.col.f32.tf32.tf32.f32 "
        "{%0,%1,%2,%3}, {%4,%5,%6,%7}, {%8,%9}, {%0,%1,%2,%3};"
        : "+f"(c[0]), "+f"(c[1]), "+f"(c[2]), "+f"(c[3])
        : "r"(a[0]), "r"(a[1]), "r"(a[2]), "r"(a[3]), "r"(b[0]), "r"(b[1]));
}

__global__ __launch_bounds__(256, 2)
void k_gemm_mma(const float* __restrict__ p2b, float* __restrict__ out) {
    extern __shared__ float sm[];
    __shared__ float sPb[128];
    int tid = threadIdx.x;
    int wid = tid >> 5, lane = tid & 31;
    int tig = lane & 3, grp = lane >> 2;
    int wm = wid & 1, wn = wid >> 1;         // warp tile: 64 rows x 32 cols
    int n0 = blockIdx.x * 128;
    int m0 = blockIdx.y * 128;
    if (tid < 128) sPb[tid] = p2b[n0 + tid];

    const float* Aop = g_q + (size_t)m0 * 256;
    const float* Bop = g_bt + (size_t)n0 * 256;

    float acc[4][4][4];
#pragma unroll
    for (int i = 0; i < 4; i++)
#pragma unroll
        for (int j = 0; j < 4; j++)
#pragma unroll
            for (int r = 0; r < 4; r++) acc[i][j][r] = 0.f;

#define PREFETCH(ch) do {                                                     \
    int st_ = (ch) % NSTAGE;                                                  \
    float* Ab_ = sm + st_ * STAGEF;                                           \
    float* Bb_ = Ab_ + 4608;                                                  \
    int k0_ = (ch) * 32;                                                      \
    _Pragma("unroll")                                                         \
    for (int it = 0; it < 4; it++) {                                          \
        int fi = tid + it * 256;                                              \
        int row = fi >> 3, c4 = (fi & 7) * 4;                                 \
        uint32_t da = (uint32_t)__cvta_generic_to_shared(Ab_ + row * PADK + c4); \
        const float* ga = Aop + (size_t)row * 256 + k0_ + c4;                 \
        asm volatile("cp.async.cg.shared.global [%0], [%1], 16;" :: "r"(da), "l"(ga)); \
        uint32_t db = (uint32_t)__cvta_generic_to_shared(Bb_ + row * PADK + c4); \
        const float* gb = Bop + (size_t)row * 256 + k0_ + c4;                 \
        asm volatile("cp.async.cg.shared.global [%0], [%1], 16;" :: "r"(db), "l"(gb)); \
    }                                                                         \
    asm volatile("cp.async.commit_group;" ::: "memory");                      \
} while (0)

    PREFETCH(0);
    PREFETCH(1);

    for (int ch = 0; ch < 8; ch++) {
        if (ch < 7) {
            asm volatile("cp.async.wait_group 1;" ::: "memory");
        } else {
            asm volatile("cp.async.wait_group 0;" ::: "memory");
        }
        __syncthreads();
        const float* Ab = sm + (ch % NSTAGE) * STAGEF;
        const float* Bb = Ab + 4608;

#pragma unroll
        for (int kk = 0; kk < 4; kk++) {
            int kb = kk * 8;
            uint32_t af[4][4], bf[4][2];
#pragma unroll
            for (int mt = 0; mt < 4; mt++) {
                int r0 = wm * 64 + mt * 16 + grp;
                af[mt][0] = __float_as_uint(Ab[r0 * PADK + kb + tig]);
                af[mt][1] = __float_as_uint(Ab[(r0 + 8) * PADK + kb + tig]);
                af[mt][2] = __float_as_uint(Ab[r0 * PADK + kb + tig + 4]);
                af[mt][3] = __float_as_uint(Ab[(r0 + 8) * PADK + kb + tig + 4]);
            }
#pragma unroll
            for (int nt = 0; nt < 4; nt++) {
                int e = wn * 32 + nt * 8 + grp;
                bf[nt][0] = __float_as_uint(Bb[e * PADK + kb + tig]);
                bf[nt][1] = __float_as_uint(Bb[e * PADK + kb + tig + 4]);
            }
#pragma unroll
            for (int mt = 0; mt < 4; mt++)
#pragma unroll
                for (int nt = 0; nt < 4; nt++)
                    mma16n8k8(acc[mt][nt], af[mt], bf[nt]);
        }
        // prefetch after compute: barrier at next iter top guarantees no warp
        // is still reading stage (ch+2)%3 (it differs from ch%3 and (ch+1)%3,
        // and no warp can be behind iteration ch thanks to the barrier)
        if (ch + 2 < 8) PREFETCH(ch + 2);
    }

    // epilogue: (acc + bias) * branch, scattered but 32B-sector aligned
    float br = g_branch[m0 >> 12];
#pragma unroll
    for (int mt = 0; mt < 4; mt++) {
        int row0 = m0 + wm * 64 + mt * 16 + grp;
        int row1 = row0 + 8;
        float* o0 = out + (size_t)(row0 >> 6) * (OUTC * 64) + (row0 & 63);
        float* o1 = out + (size_t)(row1 >> 6) * (OUTC * 64) + (row1 & 63);
#pragma unroll
        for (int nt = 0; nt < 4; nt++) {
            int el = wn * 32 + nt * 8 + 2 * tig;     // local e in [0,128)
            int e = n0 + el;
            float b0 = sPb[el], b1 = sPb[el + 1];
            __stcs(o0 + (size_t)e * 64,       (acc[mt][nt][0] + b0) * br);
            __stcs(o0 + (size_t)(e + 1) * 64, (acc[mt][nt][1] + b1) * br);
            __stcs(o1 + (size_t)e * 64,       (acc[mt][nt][2] + b0) * br);
            __stcs(o1 + (size_t)(e + 1) * 64, (acc[mt][nt][3] + b1) * br);
        }
    }
#undef PREFETCH
}

#define GEMM_SMEM (NSTAGE * STAGEF * 4)   /* 110592 bytes */

// ---------------- launch ------------------------------------------------------
extern "C" void kernel_launch(void* const* d_in, const int* in_sizes, int n_in,
                              void* d_out, int out_size) {
    const float* x     = (const float*)d_in[0];
    const float* cond  = (const float*)d_in[1];
    const float* bn2_g = (const float*)d_in[2];
    const float* bn2_b = (const float*)d_in[3];
    const float* bn1_g = (const float*)d_in[4];
    const float* bn1_b = (const float*)d_in[5];
    const float* b_w1  = (const float*)d_in[6];
    const float* b_b1  = (const float*)d_in[7];
    const float* b_w2  = (const float*)d_in[8];
    const float* b_b2  = (const float*)d_in[9];
    const float* b_w3  = (const float*)d_in[10];
    const float* b_b3  = (const float*)d_in[11];
    const float* l1_w  = (const float*)d_in[12];
    const float* l1_b  = (const float*)d_in[13];
    const float* l2_w  = (const float*)d_in[14];
    const float* l2_b  = (const float*)d_in[15];
    const float* sw1r  = (const float*)d_in[16];
    const float* sw1i  = (const float*)d_in[17];
    const float* sw2r  = (const float*)d_in[18];
    const float* sw2i  = (const float*)d_in[19];
    const float* sk_w  = (const float*)d_in[20];
    const float* sk_b  = (const float*)d_in[21];
    const float* p1_w  = (const float*)d_in[22];
    const float* p1_b  = (const float*)d_in[23];
    const float* p2_w  = (const float*)d_in[24];
    const float* p2_b  = (const float*)d_in[25];
    float* out = (float*)d_out;

    cudaFuncSetAttribute(k_gemm_mma, cudaFuncAttributeMaxDynamicSharedMemorySize, GEMM_SMEM);

    k_init_tw<<<1, 64>>>();
    k_gtab<<<(GT_N + 256) / 256, 256>>>();
    k_stats<<<1, 1024>>>(x, bn2_g, bn2_b);
    k_branch<<<1, 64>>>(cond, bn1_g, bn1_b, b_w1, b_b1, b_w2, b_b2, b_w3, b_b3);
    k_tab<<<(TAB_N + 64) / 64, 256>>>(l1_w, l1_b, l2_w, l2_b);
    k_lift<<<NPIX / 256, 256>>>(x);

    dim3 tg(OUTC / 32, 256 / 32);
    k_transp<<<tg, dim3(32, 32)>>>(p2_w);

    for (int lay = 0; lay < 4; lay++) {
        int in_flag = lay & 1;   // 0: g_t0 in, 1: g_t1 in
        k_fwd<<<BB * HID, 512>>>(in_flag);
        k_spec<<<(BB * HID * 32 * 16) / 256, 256>>>(lay, sw1r, sw1i, sw2r, sw2i);
        k_inv<<<BB * HID, 512>>>(lay, in_flag, sk_w, sk_b);
    }

    k_proj1<<<NPIX / 8, 256>>>(p1_w, p1_b);

    dim3 gg(OUTC / 128, NPIX / 128);
    k_gemm_mma<<<gg, 256, GEMM_SMEM>>>(p2_b, out);
}

// round 6
// speedup vs baseline: 2.1861x; 1.0839x over previous
#include <cuda_runtime.h>
#include <math.h>
#include <stdint.h>

#define BB 16
#define HH 64
#define WW 64
#define HID 12
#define MODES 16
#define LIFTC 256
#define OUTC 640
#define NPIX (BB*HH*WW)      /* 65536 */
#define HWSZ (HH*WW)         /* 4096 */
#define EPS 1e-5f
#define TAB_N 8192
#define TAB_LO (-9.0f)
#define TAB_STEP (18.0f / TAB_N)
#define TAB_INV (TAB_N / 18.0f)
#define GT_N 8192            /* gelu table: [-8, 8], step 1/512 */

// ---------------- scratch (device globals; no allocations allowed) ----------
__device__ __align__(16) float g_twc[64];
__device__ __align__(16) float g_tws[64];
__device__ float g_scale, g_shift;
__device__ float g_branch[BB];
__device__ __align__(16) float g_t0[BB*HID*HWSZ];   // 3 MB ping
__device__ __align__(16) float g_t1[BB*HID*HWSZ];   // 3 MB pong
__device__ __align__(16) float2 g_xft [BB*HID*32*MODES];  // [bc][mi][k]
__device__ __align__(16) float2 g_yft [BB*HID*32*MODES];  // [bo][mi][k]
__device__ __align__(16) float g_q[NPIX*LIFTC];           // 64 MB, [p][k], tf32-rounded
__device__ __align__(16) float g_bt[OUTC*LIFTC];          // 640 KB, [e][k], tf32-rounded
__device__ __align__(16) float g_tab[(TAB_N + 1) * 12];   // lifting lookup table
__device__ __align__(16) float g_gt[GT_N + 1];            // gelu lookup table

__device__ __forceinline__ float gelu_exact(float x) { return x * normcdff(x); }

// table gelu: linear interp on [-8,8], exact tails
__device__ __forceinline__ float gelu_tab(float a) {
    float f = fmaf(a, 512.0f, 4096.0f);
    f = fminf(fmaxf(f, 0.0f), 8191.999f);
    int i = (int)f;
    float fr = f - (float)i;
    float a0 = g_gt[i], a1 = g_gt[i + 1];
    float g = fmaf(fr, a1 - a0, a0);
    return (a >= 8.0f) ? a : g;
}

__device__ __forceinline__ float to_tf32(float x) {
    uint32_t r;
    asm("cvt.rna.tf32.f32 %0, %1;" : "=r"(r) : "f"(x));
    return __uint_as_float(r);
}

// ---------------- setup: twiddles + gelu table -------------------------------
__global__ void k_setup() {
    int idx = blockIdx.x * 256 + threadIdx.x;
    if (blockIdx.x == 0 && threadIdx.x < 64) {
        float s, c;
        sincospif((float)threadIdx.x / 32.0f, &s, &c);   // angle 2*pi*j/64
        g_twc[threadIdx.x] = c; g_tws[threadIdx.x] = s;
    }
    if (idx <= GT_N) {
        float x = -8.0f + (float)idx * (16.0f / GT_N);
        g_gt[idx] = gelu_exact(x);
    }
}

// ---------------- batchnorm2d stats over all of x ---------------------------
__global__ void k_stats(const float* __restrict__ x,
                        const float* __restrict__ g2,
                        const float* __restrict__ b2) {
    __shared__ double ssum[1024];
    __shared__ double ssq[1024];
    int tid = threadIdx.x;
    double s = 0.0, q = 0.0;
    const float4* x4 = (const float4*)x;
    for (int i = tid; i < NPIX / 4; i += 1024) {
        float4 v = x4[i];
        s += (double)v.x + (double)v.y + (double)v.z + (double)v.w;
        q += (double)v.x * v.x + (double)v.y * v.y + (double)v.z * v.z + (double)v.w * v.w;
    }
    ssum[tid] = s; ssq[tid] = q;
    __syncthreads();
    for (int o = 512; o > 0; o >>= 1) {
        if (tid < o) { ssum[tid] += ssum[tid + o]; ssq[tid] += ssq[tid + o]; }
        __syncthreads();
    }
    if (tid == 0) {
        double m = ssum[0] / (double)NPIX;
        double var = ssq[0] / (double)NPIX - m * m;
        float rstd = rsqrtf((float)var + EPS);
        float sc = g2[0] * rstd;
        g_scale = sc;
        g_shift = b2[0] - (float)m * sc;
    }
}

// ---------------- condition BN + branch MLP (warp per sample) ---------------
__global__ __launch_bounds__(512)
void k_branch(const float* __restrict__ cond,
              const float* __restrict__ g1, const float* __restrict__ b1,
              const float* __restrict__ w1, const float* __restrict__ bb1,
              const float* __restrict__ w2, const float* __restrict__ bb2,
              const float* __restrict__ w3, const float* __restrict__ bb3) {
    __shared__ float w1s[100], b1s[50], w2s[2500], b2s[50], w3s[50], b3s;
    __shared__ float cs[2], cb[2];
    __shared__ float h1s[16][52];
    int tid = threadIdx.x;
    int w = tid >> 5, lane = tid & 31;

    if (tid < 100) w1s[tid] = w1[tid];
    if (tid >= 128 && tid < 178) b1s[tid - 128] = bb1[tid - 128];
    if (tid >= 192 && tid < 242) b2s[tid - 192] = bb2[tid - 192];
    if (tid >= 256 && tid < 306) w3s[tid - 256] = w3[tid - 256];
    if (tid == 320) b3s = bb3[0];
    for (int i = tid; i < 2500; i += 512) w2s[i] = w2[i];
    if (tid < 2) {
        float m = 0.f;
        for (int b = 0; b < BB; b++) m += cond[b * 2 + tid];
        m /= (float)BB;
        float v = 0.f;
        for (int b = 0; b < BB; b++) { float d = cond[b * 2 + tid] - m; v += d * d; }
        v /= (float)BB;
        float sc = rsqrtf(v + EPS) * g1[tid];
        cs[tid] = sc;
        cb[tid] = b1[tid] - m * sc;
    }
    __syncthreads();

    float c0 = cond[w * 2 + 0] * cs[0] + cb[0];
    float c1 = cond[w * 2 + 1] * cs[1] + cb[1];
    for (int j = lane; j < 50; j += 32)
        h1s[w][j] = tanhf(c0 * w1s[j] + c1 * w1s[50 + j] + b1s[j]);
    __syncwarp();

    float part = 0.f;
    for (int j = lane; j < 50; j += 32) {
        float a = b2s[j];
#pragma unroll 10
        for (int k = 0; k < 50; k++) a = fmaf(h1s[w][k], w2s[k * 50 + j], a);
        part += tanhf(a) * w3s[j];
    }
#pragma unroll
    for (int o = 16; o > 0; o >>= 1)
        part += __shfl_down_sync(0xffffffff, part, o);
    if (lane == 0) g_branch[w] = tanhf(part + b3s);
}

// ---------------- build lifting lookup table (d-parallel) --------------------
__global__ void k_tab(const float* __restrict__ l1w, const float* __restrict__ l1b,
                      const float* __restrict__ l2w, const float* __restrict__ l2b) {
    __shared__ float s1w[256], s1b[256], s2w[256 * 12], s2b[12];
    __shared__ float red[3][64][12];
    int tid = threadIdx.x;
    s1w[tid] = l1w[tid];
    s1b[tid] = l1b[tid];
    for (int i = tid; i < 256 * 12; i += 256) s2w[i] = l2w[i];
    if (tid < 12) s2b[tid] = l2b[tid];
    __syncthreads();

    int pl = tid & 63, qd = tid >> 6;
    int pt = blockIdx.x * 64 + pl;
    float s = TAB_LO + (float)pt * TAB_STEP;
    float acc[12];
#pragma unroll
    for (int e = 0; e < 12; e++) acc[e] = 0.f;
    int d0 = qd * 64;
    for (int d = d0; d < d0 + 64; d++) {
        float u = fmaf(s, s1w[d], s1b[d]);
        float gl = gelu_exact(u);
#pragma unroll
        for (int e = 0; e < 12; e++) acc[e] = fmaf(gl, s2w[d * 12 + e], acc[e]);
    }
    if (qd > 0) {
#pragma unroll
        for (int e = 0; e < 12; e++) red[qd - 1][pl][e] = acc[e];
    }
    __syncthreads();
    if (qd == 0 && pt <= TAB_N) {
#pragma unroll
        for (int e = 0; e < 12; e++)
            g_tab[pt * 12 + e] = acc[e] + red[0][pl][e] + red[1][pl][e] + red[2][pl][e] + s2b[e];
    }
}

// ---------------- lifting via table interp ----------------------------------
__global__ void k_lift(const float* __restrict__ x) {
    int p = blockIdx.x * 256 + threadIdx.x;
    float s = x[p] * g_scale + g_shift;
    float f = (s - TAB_LO) * TAB_INV;
    f = fminf(fmaxf(f, 0.0f), (float)TAB_N - 0.0005f);
    int i0 = (int)f;
    float fr = f - (float)i0;
    const float* ta = g_tab + i0 * 12;
    int b = p >> 12, hw = p & 4095;
#pragma unroll
    for (int e = 0; e < 12; e++) {
        float a = ta[e], bb = ta[12 + e];
        g_t0[(b * HID + e) * HWSZ + hw] = fmaf(fr, bb - a, a);
    }
}

// ---------------- fused forward DFT (W then H), block per (b,c) -------------
__global__ __launch_bounds__(512)
void k_fwd(int in_flag) {
    const float* tin = in_flag ? g_t1 : g_t0;
    __shared__ float ts[4096];
    __shared__ float2 xc[64 * 16];   // [h][k]
    __shared__ float twc[64], tws[64];
    int tid = threadIdx.x;
    int bc = blockIdx.x;
    if (tid < 64) { twc[tid] = g_twc[tid]; tws[tid] = g_tws[tid]; }
#pragma unroll
    for (int i = 0; i < 2; i++)
        *(float4*)&ts[(tid + i * 512) * 4] = *(const float4*)&tin[bc * HWSZ + (tid + i * 512) * 4];
    __syncthreads();

    // stage 1: W-DFT -> xc[h][k], 1024 outputs, 2 per thread
#pragma unroll
    for (int r = 0; r < 2; r++) {
        int o = tid + r * 512;
        int h = o >> 4, k = o & 15;
        float re = 0.f, im = 0.f;
#pragma unroll 8
        for (int w = 0; w < 64; w++) {
            int j = (w * k) & 63;
            float v = ts[h * 64 + w];
            re = fmaf(v, twc[j], re);
            im = fmaf(-v, tws[j], im);
        }
        xc[h * 16 + k] = make_float2(re, im);
    }
    __syncthreads();

    // stage 2: H-DFT at 32 mode rows -> g_xft, 512 outputs, 1 per thread
    int mi = tid >> 4, k = tid & 15;
    int m = mi + (mi >= 16 ? 32 : 0);
    float re = 0.f, im = 0.f;
#pragma unroll 8
    for (int h = 0; h < 64; h++) {
        int j = (h * m) & 63;
        float2 v = xc[h * 16 + k];
        float c = twc[j], s = tws[j];
        re += v.x * c + v.y * s;   // * e^{-i theta}
        im += v.y * c - v.x * s;
    }
    g_xft[(bc * 32 + mi) * 16 + k] = make_float2(re, im);
}

// ---------------- spectral channel mix 12 -> 12 ------------------------------
__global__ void k_spec(int lay,
                       const float* __restrict__ sw1r, const float* __restrict__ sw1i,
                       const float* __restrict__ sw2r, const float* __restrict__ sw2i) {
    int idx = blockIdx.x * 256 + threadIdx.x;   // [b][o][mi][k]
    int k = idx & 15;
    int mi = (idx >> 4) & 31;
    int bo = idx >> 9;
    int o = bo % 12, b = bo / 12;
    const float* wr = (mi < 16) ? sw1r : sw2r;
    const float* wi = (mi < 16) ? sw1i : sw2i;
    int mr = (mi < 16) ? mi : mi - 16;
    float yr = 0.f, yi = 0.f;
#pragma unroll
    for (int c = 0; c < 12; c++) {
        float2 xv = g_xft[((b * 12 + c) * 32 + mi) * 16 + k];
        int off = (((lay * 12 + c) * 12 + o) * 16 + mr) * 16 + k;
        float wre = wr[off], wim = wi[off];
        yr += xv.x * wre - xv.y * wim;
        yi += xv.x * wim + xv.y * wre;
    }
    g_yft[((b * 12 + o) * 32 + mi) * 16 + k] = make_float2(yr, yi);
}

// ---------------- fused inverse DFT (H then W) + skip + gelu, per (b,o) -----
__global__ __launch_bounds__(512)
void k_inv(int lay, int in_flag,
           const float* __restrict__ skw_g,
           const float* __restrict__ skb_g) {
    const float* tin = in_flag ? g_t1 : g_t0;
    float* tout = in_flag ? g_t0 : g_t1;
    __shared__ float2 sy[32 * 16];
    __shared__ float2 Ys[64 * 16];
    __shared__ float twc[64], tws[64];
    __shared__ float skw[12];
    __shared__ float skb;
    int tid = threadIdx.x;
    int bo = blockIdx.x;
    int b = bo / 12, o = bo % 12;
    if (tid < 64) { twc[tid] = g_twc[tid]; tws[tid] = g_tws[tid]; }
    if (tid < 512) sy[tid] = g_yft[bo * 512 + tid];
    if (tid >= 64 && tid < 76) skw[tid - 64] = skw_g[((lay * 12 + (tid - 64)) * 12) + o];
    if (tid == 76) skb = skb_g[lay * 12 + o];
    __syncthreads();

    // stage 1: inverse H-DFT -> Ys[h][k], 1024 outputs, 2 per thread
#pragma unroll
    for (int r = 0; r < 2; r++) {
        int oo = tid + r * 512;
        int h = oo >> 4, k = oo & 15;
        float re = 0.f, im = 0.f;
#pragma unroll
        for (int mi = 0; mi < 32; mi++) {
            int m = mi + (mi >= 16 ? 32 : 0);
            int j = (h * m) & 63;
            float2 v = sy[mi * 16 + k];
            float c = twc[j], s = tws[j];
            re += v.x * c - v.y * s;   // * e^{+i theta}
            im += v.x * s + v.y * c;
        }
        Ys[h * 16 + k] = make_float2(re, im);
    }
    __syncthreads();

    // stage 2: inverse W-DFT + skip conv (+ gelu), 4096 px, 8 per thread
    int w = tid & 63, hg = tid >> 6;
#pragma unroll
    for (int i = 0; i < 8; i++) {
        int h = hg * 8 + i;
        const float2* yr = &Ys[h * 16];
        float v = yr[0].x;    // k=0: imaginary part discarded by irfft
#pragma unroll
        for (int k = 1; k < 16; k++) {
            int j = (w * k) & 63;
            v += 2.f * (yr[k].x * twc[j] - yr[k].y * tws[j]);
        }
        v *= (1.0f / 4096.0f);
        float sk = skb;
#pragma unroll
        for (int c = 0; c < 12; c++)
            sk = fmaf(tin[(b * 12 + c) * HWSZ + h * 64 + w], skw[c], sk);
        float rres = v + sk;
        if (lay < 3) rres = gelu_tab(rres);
        tout[(b * 12 + o) * HWSZ + h * 64 + w] = rres;
    }
}

// ---------------- transpose + tf32-round p2w: [256][640] -> g_bt[640][256] ---
__global__ void k_transp(const float* __restrict__ w) {
    __shared__ float t[32][33];
    int e0 = blockIdx.x * 32, k0 = blockIdx.y * 32;
    t[threadIdx.y][threadIdx.x] = w[(k0 + threadIdx.y) * OUTC + e0 + threadIdx.x];
    __syncthreads();
    g_bt[(e0 + threadIdx.y) * 256 + k0 + threadIdx.x] = to_tf32(t[threadIdx.x][threadIdx.y]);
}

// ---------------- projection pass 1: 12 -> 256 gelu, q[p][k] tf32-rounded ----
__global__ void k_proj1(const float* __restrict__ p1w, const float* __restrict__ p1b) {
    __shared__ float w1s[12 * 256];
    __shared__ float b1s[256];
    int tid = threadIdx.x;
    int wid = tid >> 5, lid = tid & 31;
    if (tid < 256) b1s[tid] = p1b[tid];
    for (int i = tid; i < 12 * 256; i += 256) w1s[i] = p1w[i];
    __syncthreads();

    int p = blockIdx.x * 8 + wid;
    int b = p >> 12, hw = p & 4095;
    float tv[12];
#pragma unroll
    for (int c = 0; c < 12; c++) tv[c] = g_t0[(b * 12 + c) * HWSZ + hw];

#pragma unroll
    for (int r = 0; r < 2; r++) {
        int jb = r * 128 + lid * 4;
        float4 v;
        float* vp = (float*)&v;
#pragma unroll
        for (int jj = 0; jj < 4; jj++) {
            int j = jb + jj;
            float a = b1s[j];
#pragma unroll
            for (int c = 0; c < 12; c++) a = fmaf(tv[c], w1s[c * 256 + j], a);
            vp[jj] = to_tf32(gelu_tab(a));
        }
        *(float4*)&g_q[(size_t)p * 256 + jb] = v;
    }
}

// ---------------- projection pass 2: mma.sync tf32 GEMM 65536x640x256 --------
#define PADK 36
#define STAGEF 9216   /* floats per stage: 2 * 128*36 */
#define NSTAGE 3

__device__ __forceinline__ void mma16n8k8(float* c, const uint32_t* a, const uint32_t* b) {
    asm volatile(
        "mma.sync.aligned.m16n8k8.row.col.f32.tf32.tf32.f32 "
        "{%0,%1,%2,%3}, {%4,%5,%6,%7}, {%8,%9}, {%0,%1,%2,%3};"
        : "+f"(c[0]), "+f"(c[1]), "+f"(c[2]), "+f"(c[3])
        : "r"(a[0]), "r"(a[1]), "r"(a[2]), "r"(a[3]), "r"(b[0]), "r"(b[1]));
}

__global__ __launch_bounds__(256, 2)
void k_gemm_mma(const float* __restrict__ p2b, float* __restrict__ out) {
    extern __shared__ float sm[];
    __shared__ float sPb[128];
    int tid = threadIdx.x;
    int wid = tid >> 5, lane = tid & 31;
    int tig = lane & 3, grp = lane >> 2;
    int wm = wid & 1, wn = wid >> 1;         // warp tile: 64 rows x 32 cols
    int n0 = blockIdx.x * 128;
    int m0 = blockIdx.y * 128;
    if (tid < 128) sPb[tid] = p2b[n0 + tid];

    const float* Aop = g_q + (size_t)m0 * 256;
    const float* Bop = g_bt + (size_t)n0 * 256;

    float acc[4][4][4];
#pragma unroll
    for (int i = 0; i < 4; i++)
#pragma unroll
        for (int j = 0; j < 4; j++)
#pragma unroll
            for (int r = 0; r < 4; r++) acc[i][j][r] = 0.f;

#define PREFETCH(ch) do {                                                     \
    int st_ = (ch) % NSTAGE;                                                  \
    float* Ab_ = sm + st_ * STAGEF;                                           \
    float* Bb_ = Ab_ + 4608;                                                  \
    int k0_ = (ch) * 32;                                                      \
    _Pragma("unroll")                                                         \
    for (int it = 0; it < 4; it++) {                                          \
        int fi = tid + it * 256;                                              \
        int row = fi >> 3, c4 = (fi & 7) * 4;                                 \
        uint32_t da = (uint32_t)__cvta_generic_to_shared(Ab_ + row * PADK + c4); \
        const float* ga = Aop + (size_t)row * 256 + k0_ + c4;                 \
        asm volatile("cp.async.cg.shared.global [%0], [%1], 16;" :: "r"(da), "l"(ga)); \
        uint32_t db = (uint32_t)__cvta_generic_to_shared(Bb_ + row * PADK + c4); \
        const float* gb = Bop + (size_t)row * 256 + k0_ + c4;                 \
        asm volatile("cp.async.cg.shared.global [%0], [%1], 16;" :: "r"(db), "l"(gb)); \
    }                                                                         \
    asm volatile("cp.async.commit_group;" ::: "memory");                      \
} while (0)

    PREFETCH(0);
    PREFETCH(1);

    for (int ch = 0; ch < 8; ch++) {
        if (ch < 7) {
            asm volatile("cp.async.wait_group 1;" ::: "memory");
        } else {
            asm volatile("cp.async.wait_group 0;" ::: "memory");
        }
        __syncthreads();
        const float* Ab = sm + (ch % NSTAGE) * STAGEF;
        const float* Bb = Ab + 4608;

#pragma unroll
        for (int kk = 0; kk < 4; kk++) {
            int kb = kk * 8;
            uint32_t af[4][4], bf[4][2];
#pragma unroll
            for (int mt = 0; mt < 4; mt++) {
                int r0 = wm * 64 + mt * 16 + grp;
                af[mt][0] = __float_as_uint(Ab[r0 * PADK + kb + tig]);
                af[mt][1] = __float_as_uint(Ab[(r0 + 8) * PADK + kb + tig]);
                af[mt][2] = __float_as_uint(Ab[r0 * PADK + kb + tig + 4]);
                af[mt][3] = __float_as_uint(Ab[(r0 + 8) * PADK + kb + tig + 4]);
            }
#pragma unroll
            for (int nt = 0; nt < 4; nt++) {
                int e = wn * 32 + nt * 8 + grp;
                bf[nt][0] = __float_as_uint(Bb[e * PADK + kb + tig]);
                bf[nt][1] = __float_as_uint(Bb[e * PADK + kb + tig + 4]);
            }
#pragma unroll
            for (int mt = 0; mt < 4; mt++)
#pragma unroll
                for (int nt = 0; nt < 4; nt++)
                    mma16n8k8(acc[mt][nt], af[mt], bf[nt]);
        }
        // prefetch after compute: barrier at next iter top guarantees no warp
        // is still reading stage (ch+2)%3
        if (ch + 2 < 8) PREFETCH(ch + 2);
    }

    // epilogue: (acc + bias) * branch, scattered but 32B-sector aligned
    float br = g_branch[m0 >> 12];
#pragma unroll
    for (int mt = 0; mt < 4; mt++) {
        int row0 = m0 + wm * 64 + mt * 16 + grp;
        int row1 = row0 + 8;
        float* o0 = out + (size_t)(row0 >> 6) * (OUTC * 64) + (row0 & 63);
        float* o1 = out + (size_t)(row1 >> 6) * (OUTC * 64) + (row1 & 63);
#pragma unroll
        for (int nt = 0; nt < 4; nt++) {
            int el = wn * 32 + nt * 8 + 2 * tig;     // local e in [0,128)
            int e = n0 + el;
            float b0 = sPb[el], b1 = sPb[el + 1];
            __stcs(o0 + (size_t)e * 64,       (acc[mt][nt][0] + b0) * br);
            __stcs(o0 + (size_t)(e + 1) * 64, (acc[mt][nt][1] + b1) * br);
            __stcs(o1 + (size_t)e * 64,       (acc[mt][nt][2] + b0) * br);
            __stcs(o1 + (size_t)(e + 1) * 64, (acc[mt][nt][3] + b1) * br);
        }
    }
#undef PREFETCH
}

#define GEMM_SMEM (NSTAGE * STAGEF * 4)   /* 110592 bytes */

// ---------------- launch ------------------------------------------------------
extern "C" void kernel_launch(void* const* d_in, const int* in_sizes, int n_in,
                              void* d_out, int out_size) {
    const float* x     = (const float*)d_in[0];
    const float* cond  = (const float*)d_in[1];
    const float* bn2_g = (const float*)d_in[2];
    const float* bn2_b = (const float*)d_in[3];
    const float* bn1_g = (const float*)d_in[4];
    const float* bn1_b = (const float*)d_in[5];
    const float* b_w1  = (const float*)d_in[6];
    const float* b_b1  = (const float*)d_in[7];
    const float* b_w2  = (const float*)d_in[8];
    const float* b_b2  = (const float*)d_in[9];
    const float* b_w3  = (const float*)d_in[10];
    const float* b_b3  = (const float*)d_in[11];
    const float* l1_w  = (const float*)d_in[12];
    const float* l1_b  = (const float*)d_in[13];
    const float* l2_w  = (const float*)d_in[14];
    const float* l2_b  = (const float*)d_in[15];
    const float* sw1r  = (const float*)d_in[16];
    const float* sw1i  = (const float*)d_in[17];
    const float* sw2r  = (const float*)d_in[18];
    const float* sw2i  = (const float*)d_in[19];
    const float* sk_w  = (const float*)d_in[20];
    const float* sk_b  = (const float*)d_in[21];
    const float* p1_w  = (const float*)d_in[22];
    const float* p1_b  = (const float*)d_in[23];
    const float* p2_w  = (const float*)d_in[24];
    const float* p2_b  = (const float*)d_in[25];
    float* out = (float*)d_out;

    cudaFuncSetAttribute(k_gemm_mma, cudaFuncAttributeMaxDynamicSharedMemorySize, GEMM_SMEM);

    k_setup<<<(GT_N + 256) / 256, 256>>>();
    k_stats<<<1, 1024>>>(x, bn2_g, bn2_b);
    k_branch<<<1, 512>>>(cond, bn1_g, bn1_b, b_w1, b_b1, b_w2, b_b2, b_w3, b_b3);
    k_tab<<<(TAB_N + 64) / 64, 256>>>(l1_w, l1_b, l2_w, l2_b);
    k_lift<<<NPIX / 256, 256>>>(x);

    dim3 tg(OUTC / 32, 256 / 32);
    k_transp<<<tg, dim3(32, 32)>>>(p2_w);

    for (int lay = 0; lay < 4; lay++) {
        int in_flag = lay & 1;   // 0: g_t0 in, 1: g_t1 in
        k_fwd<<<BB * HID, 512>>>(in_flag);
        k_spec<<<(BB * HID * 32 * 16) / 256, 256>>>(lay, sw1r, sw1i, sw2r, sw2i);
        k_inv<<<BB * HID, 512>>>(lay, in_flag, sk_w, sk_b);
    }

    k_proj1<<<NPIX / 8, 256>>>(p1_w, p1_b);

    dim3 gg(OUTC / 128, NPIX / 128);
    k_gemm_mma<<<gg, 256, GEMM_SMEM>>>(p2_b, out);
}

// round 7
// speedup vs baseline: 2.2513x; 1.0298x over previous
#include <cuda_runtime.h>
#include <math.h>
#include <stdint.h>

#define BB 16
#define HH 64
#define WW 64
#define HID 12
#define MODES 16
#define LIFTC 256
#define OUTC 640
#define NPIX (BB*HH*WW)      /* 65536 */
#define HWSZ (HH*WW)         /* 4096 */
#define EPS 1e-5f
#define TAB_N 8192
#define TAB_LO (-9.0f)
#define TAB_STEP (18.0f / TAB_N)
#define TAB_INV (TAB_N / 18.0f)
#define GT_N 8192            /* gelu table: [-8, 8], step 1/512 */

// ---------------- scratch (device globals; no allocations allowed) ----------
__device__ __align__(16) float2 g_tw[64];           // (cos, sin) interleaved
__device__ float g_scale, g_shift;
__device__ float g_branch[BB];
__device__ __align__(16) float g_t0[BB*HID*HWSZ];   // 3 MB ping
__device__ __align__(16) float g_t1[BB*HID*HWSZ];   // 3 MB pong
__device__ __align__(16) float2 g_xftA[BB*HID*32*MODES];  // spectrum ping
__device__ __align__(16) float2 g_xftB[BB*HID*32*MODES];  // spectrum pong
__device__ __align__(16) float g_q[NPIX*LIFTC];           // 64 MB, [p][k], tf32-rounded
__device__ __align__(16) float g_bt[OUTC*LIFTC];          // 640 KB, [e][k], tf32-rounded
__device__ __align__(16) float g_tab[(TAB_N + 1) * 12];   // lifting lookup table
__device__ __align__(16) float g_gt[GT_N + 1];            // gelu lookup table

__device__ __forceinline__ float gelu_exact(float x) { return x * normcdff(x); }

// table gelu: linear interp on [-8,8], exact tails
__device__ __forceinline__ float gelu_tab(float a) {
    float f = fmaf(a, 512.0f, 4096.0f);
    f = fminf(fmaxf(f, 0.0f), 8191.999f);
    int i = (int)f;
    float fr = f - (float)i;
    float a0 = g_gt[i], a1 = g_gt[i + 1];
    float g = fmaf(fr, a1 - a0, a0);
    return (a >= 8.0f) ? a : g;
}

__device__ __forceinline__ float to_tf32(float x) {
    uint32_t r;
    asm("cvt.rna.tf32.f32 %0, %1;" : "=r"(r) : "f"(x));
    return __uint_as_float(r);
}

// ---------------- setup: twiddles + gelu table -------------------------------
__global__ void k_setup() {
    int idx = blockIdx.x * 256 + threadIdx.x;
    if (blockIdx.x == 0 && threadIdx.x < 64) {
        float s, c;
        sincospif((float)threadIdx.x / 32.0f, &s, &c);   // angle 2*pi*j/64
        g_tw[threadIdx.x] = make_float2(c, s);
    }
    if (idx <= GT_N) {
        float x = -8.0f + (float)idx * (16.0f / GT_N);
        g_gt[idx] = gelu_exact(x);
    }
}

// ---------------- batchnorm2d stats over all of x ---------------------------
__global__ void k_stats(const float* __restrict__ x,
                        const float* __restrict__ g2,
                        const float* __restrict__ b2) {
    __shared__ double ssum[1024];
    __shared__ double ssq[1024];
    int tid = threadIdx.x;
    double s = 0.0, q = 0.0;
    const float4* x4 = (const float4*)x;
    for (int i = tid; i < NPIX / 4; i += 1024) {
        float4 v = x4[i];
        s += (double)v.x + (double)v.y + (double)v.z + (double)v.w;
        q += (double)v.x * v.x + (double)v.y * v.y + (double)v.z * v.z + (double)v.w * v.w;
    }
    ssum[tid] = s; ssq[tid] = q;
    __syncthreads();
    for (int o = 512; o > 0; o >>= 1) {
        if (tid < o) { ssum[tid] += ssum[tid + o]; ssq[tid] += ssq[tid + o]; }
        __syncthreads();
    }
    if (tid == 0) {
        double m = ssum[0] / (double)NPIX;
        double var = ssq[0] / (double)NPIX - m * m;
        float rstd = rsqrtf((float)var + EPS);
        float sc = g2[0] * rstd;
        g_scale = sc;
        g_shift = b2[0] - (float)m * sc;
    }
}

// ---------------- condition BN + branch MLP (warp per sample) ---------------
__global__ __launch_bounds__(512)
void k_branch(const float* __restrict__ cond,
              const float* __restrict__ g1, const float* __restrict__ b1,
              const float* __restrict__ w1, const float* __restrict__ bb1,
              const float* __restrict__ w2, const float* __restrict__ bb2,
              const float* __restrict__ w3, const float* __restrict__ bb3) {
    __shared__ float w1s[100], b1s[50], w2s[2500], b2s[50], w3s[50], b3s;
    __shared__ float cs[2], cb[2];
    __shared__ float h1s[16][52];
    int tid = threadIdx.x;
    int w = tid >> 5, lane = tid & 31;

    if (tid < 100) w1s[tid] = w1[tid];
    if (tid >= 128 && tid < 178) b1s[tid - 128] = bb1[tid - 128];
    if (tid >= 192 && tid < 242) b2s[tid - 192] = bb2[tid - 192];
    if (tid >= 256 && tid < 306) w3s[tid - 256] = w3[tid - 256];
    if (tid == 320) b3s = bb3[0];
    for (int i = tid; i < 2500; i += 512) w2s[i] = w2[i];
    if (tid < 2) {
        float m = 0.f;
        for (int b = 0; b < BB; b++) m += cond[b * 2 + tid];
        m /= (float)BB;
        float v = 0.f;
        for (int b = 0; b < BB; b++) { float d = cond[b * 2 + tid] - m; v += d * d; }
        v /= (float)BB;
        float sc = rsqrtf(v + EPS) * g1[tid];
        cs[tid] = sc;
        cb[tid] = b1[tid] - m * sc;
    }
    __syncthreads();

    float c0 = cond[w * 2 + 0] * cs[0] + cb[0];
    float c1 = cond[w * 2 + 1] * cs[1] + cb[1];
    for (int j = lane; j < 50; j += 32)
        h1s[w][j] = tanhf(c0 * w1s[j] + c1 * w1s[50 + j] + b1s[j]);
    __syncwarp();

    float part = 0.f;
    for (int j = lane; j < 50; j += 32) {
        float a = b2s[j];
#pragma unroll 10
        for (int k = 0; k < 50; k++) a = fmaf(h1s[w][k], w2s[k * 50 + j], a);
        part += tanhf(a) * w3s[j];
    }
#pragma unroll
    for (int o = 16; o > 0; o >>= 1)
        part += __shfl_down_sync(0xffffffff, part, o);
    if (lane == 0) g_branch[w] = tanhf(part + b3s);
}

// ---------------- build lifting lookup table (8-way d-parallel) --------------
__global__ __launch_bounds__(512)
void k_tab(const float* __restrict__ l1w, const float* __restrict__ l1b,
           const float* __restrict__ l2w, const float* __restrict__ l2b) {
    __shared__ float s1w[256], s1b[256], s2w[256 * 12], s2b[12];
    __shared__ float red[7][64][12];
    int tid = threadIdx.x;
    if (tid < 256) { s1w[tid] = l1w[tid]; s1b[tid] = l1b[tid]; }
    for (int i = tid; i < 256 * 12; i += 512) s2w[i] = l2w[i];
    if (tid >= 256 && tid < 268) s2b[tid - 256] = l2b[tid - 256];
    __syncthreads();

    int pl = tid & 63, qd = tid >> 6;   // 64 points x 8 d-groups
    int pt = blockIdx.x * 64 + pl;
    float s = TAB_LO + (float)pt * TAB_STEP;
    float acc[12];
#pragma unroll
    for (int e = 0; e < 12; e++) acc[e] = 0.f;
    int d0 = qd * 32;
    for (int d = d0; d < d0 + 32; d++) {
        float u = fmaf(s, s1w[d], s1b[d]);
        float gl = gelu_exact(u);
#pragma unroll
        for (int e = 0; e < 12; e++) acc[e] = fmaf(gl, s2w[d * 12 + e], acc[e]);
    }
    if (qd > 0) {
#pragma unroll
        for (int e = 0; e < 12; e++) red[qd - 1][pl][e] = acc[e];
    }
    __syncthreads();
    if (qd == 0 && pt <= TAB_N) {
        float r[12];
#pragma unroll
        for (int e = 0; e < 12; e++) r[e] = acc[e] + s2b[e];
#pragma unroll
        for (int g = 0; g < 7; g++)
#pragma unroll
            for (int e = 0; e < 12; e++) r[e] += red[g][pl][e];
#pragma unroll
        for (int e = 0; e < 12; e++) g_tab[pt * 12 + e] = r[e];
    }
}

// ---------------- lifting via table interp ----------------------------------
__global__ void k_lift(const float* __restrict__ x) {
    int p = blockIdx.x * 256 + threadIdx.x;
    float s = x[p] * g_scale + g_shift;
    float f = (s - TAB_LO) * TAB_INV;
    f = fminf(fmaxf(f, 0.0f), (float)TAB_N - 0.0005f);
    int i0 = (int)f;
    float fr = f - (float)i0;
    const float* ta = g_tab + i0 * 12;
    int b = p >> 12, hw = p & 4095;
#pragma unroll
    for (int e = 0; e < 12; e++) {
        float a = ta[e], bb = ta[12 + e];
        g_t0[(b * HID + e) * HWSZ + hw] = fmaf(fr, bb - a, a);
    }
}

// ---------------- forward DFT (W then H) for layer 0, block per (b,c) -------
__global__ __launch_bounds__(512)
void k_fwd0() {
    __shared__ float ts[4096];
    __shared__ float2 xc[64 * 16];   // [h][k]
    __shared__ float2 tw[64];
    int tid = threadIdx.x;
    int bc = blockIdx.x;
    if (tid < 64) tw[tid] = g_tw[tid];
#pragma unroll
    for (int i = 0; i < 2; i++)
        *(float4*)&ts[(tid + i * 512) * 4] = *(const float4*)&g_t0[bc * HWSZ + (tid + i * 512) * 4];
    __syncthreads();

#pragma unroll
    for (int r = 0; r < 2; r++) {
        int o = tid + r * 512;
        int h = o >> 4, k = o & 15;
        float re = 0.f, im = 0.f;
#pragma unroll 8
        for (int w = 0; w < 64; w++) {
            float2 t = tw[(w * k) & 63];
            float v = ts[h * 64 + w];
            re = fmaf(v, t.x, re);
            im = fmaf(-v, t.y, im);
        }
        xc[h * 16 + k] = make_float2(re, im);
    }
    __syncthreads();

    int mi = tid >> 4, k = tid & 15;
    int m = mi + (mi >= 16 ? 32 : 0);
    float re = 0.f, im = 0.f;
#pragma unroll 8
    for (int h = 0; h < 64; h++) {
        float2 t = tw[(h * m) & 63];
        float2 v = xc[h * 16 + k];
        re += v.x * t.x + v.y * t.y;   // * e^{-i theta}
        im += v.y * t.x - v.x * t.y;
    }
    g_xftA[(bc * 32 + mi) * 16 + k] = make_float2(re, im);
}

// ---------------- fused layer: spec + invH + invW/skip/gelu + fwdW + fwdH ----
// block per (b,o). reads xft_in (all 12 c of b), writes tout, xft_out.
__global__ __launch_bounds__(512)
void k_layer(int lay,
             const float* __restrict__ sw1r, const float* __restrict__ sw1i,
             const float* __restrict__ sw2r, const float* __restrict__ sw2i,
             const float* __restrict__ skw_g, const float* __restrict__ skb_g) {
    const int in_flag = lay & 1;
    const float* tin = in_flag ? g_t1 : g_t0;
    float* tout = in_flag ? g_t0 : g_t1;
    const float2* xft_in = in_flag ? g_xftB : g_xftA;
    float2* xft_out = in_flag ? g_xftA : g_xftB;

    __shared__ float2 sy[32 * 16];     // spec output  [mi][k]
    __shared__ float2 Ys[64 * 16];     // invH output  [h][k]
    __shared__ float ts[4096];         // spatial field
    __shared__ float2 xc[64 * 16];     // fwdW output  [h][k]
    __shared__ float2 tw[64];
    __shared__ float skw[12];
    __shared__ float skb;

    int tid = threadIdx.x;
    int bo = blockIdx.x;
    int b = bo / 12, o = bo % 12;
    if (tid < 64) tw[tid] = g_tw[tid];
    if (tid >= 64 && tid < 76) skw[tid - 64] = skw_g[((lay * 12 + (tid - 64)) * 12) + o];
    if (tid == 76) skb = skb_g[lay * 12 + o];

    // ---- stage 1: spectral mix (one output per thread) ----
    {
        int k = tid & 15, mi = tid >> 4;
        const float* wr = (mi < 16) ? sw1r : sw2r;
        const float* wi = (mi < 16) ? sw1i : sw2i;
        int mr = (mi < 16) ? mi : mi - 16;
        float yr = 0.f, yi = 0.f;
#pragma unroll
        for (int c = 0; c < 12; c++) {
            float2 xv = xft_in[((b * 12 + c) * 32 + mi) * 16 + k];
            int off = (((lay * 12 + c) * 12 + o) * 16 + mr) * 16 + k;
            float wre = wr[off], wim = wi[off];
            yr += xv.x * wre - xv.y * wim;
            yi += xv.x * wim + xv.y * wre;
        }
        sy[tid] = make_float2(yr, yi);
    }
    __syncthreads();

    // ---- stage 2: inverse H-DFT (2 outputs per thread) ----
#pragma unroll
    for (int r = 0; r < 2; r++) {
        int oo = tid + r * 512;
        int h = oo >> 4, k = oo & 15;
        float re = 0.f, im = 0.f;
#pragma unroll
        for (int mi = 0; mi < 32; mi++) {
            int m = mi + (mi >= 16 ? 32 : 0);
            float2 t = tw[(h * m) & 63];
            float2 v = sy[mi * 16 + k];
            re += v.x * t.x - v.y * t.y;   // * e^{+i theta}
            im += v.x * t.y + v.y * t.x;
        }
        Ys[h * 16 + k] = make_float2(re, im);
    }
    __syncthreads();

    // ---- stage 3: inverse W-DFT + skip conv (+ gelu), 8 px per thread ----
    {
        int w = tid & 63, hg = tid >> 6;
#pragma unroll
        for (int i = 0; i < 8; i++) {
            int h = hg * 8 + i;
            const float2* yr = &Ys[h * 16];
            float v = yr[0].x;    // k=0: imaginary part discarded by irfft
#pragma unroll
            for (int k = 1; k < 16; k++) {
                float2 t = tw[(w * k) & 63];
                v += 2.f * (yr[k].x * t.x - yr[k].y * t.y);
            }
            v *= (1.0f / 4096.0f);
            float sk = skb;
#pragma unroll
            for (int c = 0; c < 12; c++)
                sk = fmaf(tin[(b * 12 + c) * HWSZ + h * 64 + w], skw[c], sk);
            float rres = v + sk;
            if (lay < 3) rres = gelu_tab(rres);
            ts[h * 64 + w] = rres;
            tout[(b * 12 + o) * HWSZ + h * 64 + w] = rres;
        }
    }
    if (lay == 3) return;
    __syncthreads();

    // ---- stage 4: forward W-DFT (2 outputs per thread) ----
#pragma unroll
    for (int r = 0; r < 2; r++) {
        int oo = tid + r * 512;
        int h = oo >> 4, k = oo & 15;
        float re = 0.f, im = 0.f;
#pragma unroll 8
        for (int w = 0; w < 64; w++) {
            float2 t = tw[(w * k) & 63];
            float v = ts[h * 64 + w];
            re = fmaf(v, t.x, re);
            im = fmaf(-v, t.y, im);
        }
        xc[h * 16 + k] = make_float2(re, im);
    }
    __syncthreads();

    // ---- stage 5: forward H-DFT (1 output per thread) ----
    {
        int mi = tid >> 4, k = tid & 15;
        int m = mi + (mi >= 16 ? 32 : 0);
        float re = 0.f, im = 0.f;
#pragma unroll 8
        for (int h = 0; h < 64; h++) {
            float2 t = tw[(h * m) & 63];
            float2 v = xc[h * 16 + k];
            re += v.x * t.x + v.y * t.y;   // * e^{-i theta}
            im += v.y * t.x - v.x * t.y;
        }
        xft_out[(bo * 32 + mi) * 16 + k] = make_float2(re, im);
    }
}

// ---------------- transpose + tf32-round p2w: [256][640] -> g_bt[640][256] ---
__global__ void k_transp(const float* __restrict__ w) {
    __shared__ float t[32][33];
    int e0 = blockIdx.x * 32, k0 = blockIdx.y * 32;
    t[threadIdx.y][threadIdx.x] = w[(k0 + threadIdx.y) * OUTC + e0 + threadIdx.x];
    __syncthreads();
    g_bt[(e0 + threadIdx.y) * 256 + k0 + threadIdx.x] = to_tf32(t[threadIdx.x][threadIdx.y]);
}

// ---------------- projection pass 1: 12 -> 256 gelu, q[p][k] tf32-rounded ----
__global__ void k_proj1(const float* __restrict__ p1w, const float* __restrict__ p1b) {
    __shared__ float w1s[12 * 256];
    __shared__ float b1s[256];
    int tid = threadIdx.x;
    int wid = tid >> 5, lid = tid & 31;
    if (tid < 256) b1s[tid] = p1b[tid];
    for (int i = tid; i < 12 * 256; i += 256) w1s[i] = p1w[i];
    __syncthreads();

    int p = blockIdx.x * 8 + wid;
    int b = p >> 12, hw = p & 4095;
    float tv[12];
#pragma unroll
    for (int c = 0; c < 12; c++) tv[c] = g_t0[(b * 12 + c) * HWSZ + hw];

#pragma unroll
    for (int r = 0; r < 2; r++) {
        int jb = r * 128 + lid * 4;
        float4 v;
        float* vp = (float*)&v;
#pragma unroll
        for (int jj = 0; jj < 4; jj++) {
            int j = jb + jj;
            float a = b1s[j];
#pragma unroll
            for (int c = 0; c < 12; c++) a = fmaf(tv[c], w1s[c * 256 + j], a);
            vp[jj] = to_tf32(gelu_tab(a));
        }
        *(float4*)&g_q[(size_t)p * 256 + jb] = v;
    }
}

// ---------------- projection pass 2: mma.sync tf32 GEMM 65536x640x256 --------
#define PADK 36
#define STAGEF 9216   /* floats per stage: 2 * 128*36 */
#define NSTAGE 3

__device__ __forceinline__ void mma16n8k8(float* c, const uint32_t* a, const uint32_t* b) {
    asm volatile(
        "mma.sync.aligned.m16n8k8.row.col.f32.tf32.tf32.f32 "
        "{%0,%1,%2,%3}, {%4,%5,%6,%7}, {%8,%9}, {%0,%1,%2,%3};"
        : "+f"(c[0]), "+f"(c[1]), "+f"(c[2]), "+f"(c[3])
        : "r"(a[0]), "r"(a[1]), "r"(a[2]), "r"(a[3]), "r"(b[0]), "r"(b[1]));
}

__global__ __launch_bounds__(256, 2)
void k_gemm_mma(const float* __restrict__ p2b, float* __restrict__ out) {
    extern __shared__ float sm[];
    __shared__ float sPb[128];
    int tid = threadIdx.x;
    int wid = tid >> 5, lane = tid & 31;
    int tig = lane & 3, grp = lane >> 2;
    int wm = wid & 1, wn = wid >> 1;         // warp tile: 64 rows x 32 cols
    int n0 = blockIdx.x * 128;
    int m0 = blockIdx.y * 128;
    if (tid < 128) sPb[tid] = p2b[n0 + tid];

    const float* Aop = g_q + (size_t)m0 * 256;
    const float* Bop = g_bt + (size_t)n0 * 256;

    float acc[4][4][4];
#pragma unroll
    for (int i = 0; i < 4; i++)
#pragma unroll
        for (int j = 0; j < 4; j++)
#pragma unroll
            for (int r = 0; r < 4; r++) acc[i][j][r] = 0.f;

#define PREFETCH(ch) do {                                                     \
    int st_ = (ch) % NSTAGE;                                                  \
    float* Ab_ = sm + st_ * STAGEF;                                           \
    float* Bb_ = Ab_ + 4608;                                                  \
    int k0_ = (ch) * 32;                                                      \
    _Pragma("unroll")                                                         \
    for (int it = 0; it < 4; it++) {                                          \
        int fi = tid + it * 256;                                              \
        int row = fi >> 3, c4 = (fi & 7) * 4;                                 \
        uint32_t da = (uint32_t)__cvta_generic_to_shared(Ab_ + row * PADK + c4); \
        const float* ga = Aop + (size_t)row * 256 + k0_ + c4;                 \
        asm volatile("cp.async.cg.shared.global [%0], [%1], 16;" :: "r"(da), "l"(ga)); \
        uint32_t db = (uint32_t)__cvta_generic_to_shared(Bb_ + row * PADK + c4); \
        const float* gb = Bop + (size_t)row * 256 + k0_ + c4;                 \
        asm volatile("cp.async.cg.shared.global [%0], [%1], 16;" :: "r"(db), "l"(gb)); \
    }                                                                         \
    asm volatile("cp.async.commit_group;" ::: "memory");                      \
} while (0)

    PREFETCH(0);
    PREFETCH(1);

    for (int ch = 0; ch < 8; ch++) {
        if (ch < 7) {
            asm volatile("cp.async.wait_group 1;" ::: "memory");
        } else {
            asm volatile("cp.async.wait_group 0;" ::: "memory");
        }
        __syncthreads();
        const float* Ab = sm + (ch % NSTAGE) * STAGEF;
        const float* Bb = Ab + 4608;

#pragma unroll
        for (int kk = 0; kk < 4; kk++) {
            int kb = kk * 8;
            uint32_t af[4][4], bf[4][2];
#pragma unroll
            for (int mt = 0; mt < 4; mt++) {
                int r0 = wm * 64 + mt * 16 + grp;
                af[mt][0] = __float_as_uint(Ab[r0 * PADK + kb + tig]);
                af[mt][1] = __float_as_uint(Ab[(r0 + 8) * PADK + kb + tig]);
                af[mt][2] = __float_as_uint(Ab[r0 * PADK + kb + tig + 4]);
                af[mt][3] = __float_as_uint(Ab[(r0 + 8) * PADK + kb + tig + 4]);
            }
#pragma unroll
            for (int nt = 0; nt < 4; nt++) {
                int e = wn * 32 + nt * 8 + grp;
                bf[nt][0] = __float_as_uint(Bb[e * PADK + kb + tig]);
                bf[nt][1] = __float_as_uint(Bb[e * PADK + kb + tig + 4]);
            }
#pragma unroll
            for (int mt = 0; mt < 4; mt++)
#pragma unroll
                for (int nt = 0; nt < 4; nt++)
                    mma16n8k8(acc[mt][nt], af[mt], bf[nt]);
        }
        if (ch + 2 < 8) PREFETCH(ch + 2);
    }

    // epilogue: (acc + bias) * branch
    float br = g_branch[m0 >> 12];
#pragma unroll
    for (int mt = 0; mt < 4; mt++) {
        int row0 = m0 + wm * 64 + mt * 16 + grp;
        int row1 = row0 + 8;
        float* o0 = out + (size_t)(row0 >> 6) * (OUTC * 64) + (row0 & 63);
        float* o1 = out + (size_t)(row1 >> 6) * (OUTC * 64) + (row1 & 63);
#pragma unroll
        for (int nt = 0; nt < 4; nt++) {
            int el = wn * 32 + nt * 8 + 2 * tig;     // local e in [0,128)
            int e = n0 + el;
            float b0 = sPb[el], b1 = sPb[el + 1];
            __stcs(o0 + (size_t)e * 64,       (acc[mt][nt][0] + b0) * br);
            __stcs(o0 + (size_t)(e + 1) * 64, (acc[mt][nt][1] + b1) * br);
            __stcs(o1 + (size_t)e * 64,       (acc[mt][nt][2] + b0) * br);
            __stcs(o1 + (size_t)(e + 1) * 64, (acc[mt][nt][3] + b1) * br);
        }
    }
#undef PREFETCH
}

#define GEMM_SMEM (NSTAGE * STAGEF * 4)   /* 110592 bytes */

// ---------------- launch ------------------------------------------------------
extern "C" void kernel_launch(void* const* d_in, const int* in_sizes, int n_in,
                              void* d_out, int out_size) {
    const float* x     = (const float*)d_in[0];
    const float* cond  = (const float*)d_in[1];
    const float* bn2_g = (const float*)d_in[2];
    const float* bn2_b = (const float*)d_in[3];
    const float* bn1_g = (const float*)d_in[4];
    const float* bn1_b = (const float*)d_in[5];
    const float* b_w1  = (const float*)d_in[6];
    const float* b_b1  = (const float*)d_in[7];
    const float* b_w2  = (const float*)d_in[8];
    const float* b_b2  = (const float*)d_in[9];
    const float* b_w3  = (const float*)d_in[10];
    const float* b_b3  = (const float*)d_in[11];
    const float* l1_w  = (const float*)d_in[12];
    const float* l1_b  = (const float*)d_in[13];
    const float* l2_w  = (const float*)d_in[14];
    const float* l2_b  = (const float*)d_in[15];
    const float* sw1r  = (const float*)d_in[16];
    const float* sw1i  = (const float*)d_in[17];
    const float* sw2r  = (const float*)d_in[18];
    const float* sw2i  = (const float*)d_in[19];
    const float* sk_w  = (const float*)d_in[20];
    const float* sk_b  = (const float*)d_in[21];
    const float* p1_w  = (const float*)d_in[22];
    const float* p1_b  = (const float*)d_in[23];
    const float* p2_w  = (const float*)d_in[24];
    const float* p2_b  = (const float*)d_in[25];
    float* out = (float*)d_out;

    cudaFuncSetAttribute(k_gemm_mma, cudaFuncAttributeMaxDynamicSharedMemorySize, GEMM_SMEM);

    k_setup<<<(GT_N + 256) / 256, 256>>>();
    k_stats<<<1, 1024>>>(x, bn2_g, bn2_b);
    k_branch<<<1, 512>>>(cond, bn1_g, bn1_b, b_w1, b_b1, b_w2, b_b2, b_w3, b_b3);
    k_tab<<<(TAB_N + 64) / 64, 512>>>(l1_w, l1_b, l2_w, l2_b);
    k_lift<<<NPIX / 256, 256>>>(x);

    dim3 tg(OUTC / 32, 256 / 32);
    k_transp<<<tg, dim3(32, 32)>>>(p2_w);

    k_fwd0<<<BB * HID, 512>>>();
    for (int lay = 0; lay < 4; lay++)
        k_layer<<<BB * HID, 512>>>(lay, sw1r, sw1i, sw2r, sw2i, sk_w, sk_b);

    k_proj1<<<NPIX / 8, 256>>>(p1_w, p1_b);

    dim3 gg(OUTC / 128, NPIX / 128);
    k_gemm_mma<<<gg, 256, GEMM_SMEM>>>(p2_b, out);
}

// round 8
// speedup vs baseline: 2.6212x; 1.1643x over previous
#include <cuda_runtime.h>
#include <cuda_fp16.h>
#include <math.h>
#include <stdint.h>

#define BB 16
#define HH 64
#define WW 64
#define HID 12
#define MODES 16
#define LIFTC 256
#define OUTC 640
#define NPIX (BB*HH*WW)      /* 65536 */
#define HWSZ (HH*WW)         /* 4096 */
#define EPS 1e-5f
#define TAB_N 8192
#define TAB_LO (-9.0f)
#define TAB_STEP (18.0f / TAB_N)
#define TAB_INV (TAB_N / 18.0f)
#define GT_N 8192            /* gelu table: [-8, 8], step 1/512 */

// ---------------- scratch (device globals; no allocations allowed) ----------
__device__ __align__(16) float2 g_tw[64];           // (cos, sin) interleaved
__device__ float g_scale, g_shift;
__device__ float g_branch[BB];
__device__ __align__(16) float g_t0[BB*HID*HWSZ];   // 3 MB ping
__device__ __align__(16) float g_t1[BB*HID*HWSZ];   // 3 MB pong
__device__ __align__(16) float2 g_xftA[BB*HID*32*MODES];  // spectrum ping
__device__ __align__(16) float2 g_xftB[BB*HID*32*MODES];  // spectrum pong
__device__ __align__(16) __half g_q[NPIX*LIFTC];          // 32 MB, [p][k], fp16
__device__ __align__(16) __half g_bt[OUTC*LIFTC];         // 320 KB, [e][k], fp16
__device__ __align__(16) float g_tab[(TAB_N + 1) * 12];   // lifting lookup table
__device__ __align__(16) float g_gt[GT_N + 1];            // gelu lookup table

__device__ __forceinline__ float gelu_exact(float x) { return x * normcdff(x); }

// table gelu: linear interp on [-8,8], exact tails
__device__ __forceinline__ float gelu_tab(float a) {
    float f = fmaf(a, 512.0f, 4096.0f);
    f = fminf(fmaxf(f, 0.0f), 8191.999f);
    int i = (int)f;
    float fr = f - (float)i;
    float a0 = g_gt[i], a1 = g_gt[i + 1];
    float g = fmaf(fr, a1 - a0, a0);
    return (a >= 8.0f) ? a : g;
}

// ---------------- setup: twiddles + gelu table -------------------------------
__global__ void k_setup() {
    int idx = blockIdx.x * 256 + threadIdx.x;
    if (blockIdx.x == 0 && threadIdx.x < 64) {
        float s, c;
        sincospif((float)threadIdx.x / 32.0f, &s, &c);   // angle 2*pi*j/64
        g_tw[threadIdx.x] = make_float2(c, s);
    }
    if (idx <= GT_N) {
        float x = -8.0f + (float)idx * (16.0f / GT_N);
        g_gt[idx] = gelu_exact(x);
    }
}

// ---------------- batchnorm2d stats over all of x ---------------------------
__global__ void k_stats(const float* __restrict__ x,
                        const float* __restrict__ g2,
                        const float* __restrict__ b2) {
    __shared__ double ssum[1024];
    __shared__ double ssq[1024];
    int tid = threadIdx.x;
    double s = 0.0, q = 0.0;
    const float4* x4 = (const float4*)x;
    for (int i = tid; i < NPIX / 4; i += 1024) {
        float4 v = x4[i];
        s += (double)v.x + (double)v.y + (double)v.z + (double)v.w;
        q += (double)v.x * v.x + (double)v.y * v.y + (double)v.z * v.z + (double)v.w * v.w;
    }
    ssum[tid] = s; ssq[tid] = q;
    __syncthreads();
    for (int o = 512; o > 0; o >>= 1) {
        if (tid < o) { ssum[tid] += ssum[tid + o]; ssq[tid] += ssq[tid + o]; }
        __syncthreads();
    }
    if (tid == 0) {
        double m = ssum[0] / (double)NPIX;
        double var = ssq[0] / (double)NPIX - m * m;
        float rstd = rsqrtf((float)var + EPS);
        float sc = g2[0] * rstd;
        g_scale = sc;
        g_shift = b2[0] - (float)m * sc;
    }
}

// ---------------- condition BN + branch MLP (warp per sample) ---------------
__global__ __launch_bounds__(512)
void k_branch(const float* __restrict__ cond,
              const float* __restrict__ g1, const float* __restrict__ b1,
              const float* __restrict__ w1, const float* __restrict__ bb1,
              const float* __restrict__ w2, const float* __restrict__ bb2,
              const float* __restrict__ w3, const float* __restrict__ bb3) {
    __shared__ float w1s[100], b1s[50], w2s[2500], b2s[50], w3s[50], b3s;
    __shared__ float cs[2], cb[2];
    __shared__ float h1s[16][52];
    int tid = threadIdx.x;
    int w = tid >> 5, lane = tid & 31;

    if (tid < 100) w1s[tid] = w1[tid];
    if (tid >= 128 && tid < 178) b1s[tid - 128] = bb1[tid - 128];
    if (tid >= 192 && tid < 242) b2s[tid - 192] = bb2[tid - 192];
    if (tid >= 256 && tid < 306) w3s[tid - 256] = w3[tid - 256];
    if (tid == 320) b3s = bb3[0];
    for (int i = tid; i < 2500; i += 512) w2s[i] = w2[i];
    if (tid < 2) {
        float m = 0.f;
        for (int b = 0; b < BB; b++) m += cond[b * 2 + tid];
        m /= (float)BB;
        float v = 0.f;
        for (int b = 0; b < BB; b++) { float d = cond[b * 2 + tid] - m; v += d * d; }
        v /= (float)BB;
        float sc = rsqrtf(v + EPS) * g1[tid];
        cs[tid] = sc;
        cb[tid] = b1[tid] - m * sc;
    }
    __syncthreads();

    float c0 = cond[w * 2 + 0] * cs[0] + cb[0];
    float c1 = cond[w * 2 + 1] * cs[1] + cb[1];
    for (int j = lane; j < 50; j += 32)
        h1s[w][j] = tanhf(c0 * w1s[j] + c1 * w1s[50 + j] + b1s[j]);
    __syncwarp();

    float part = 0.f;
    for (int j = lane; j < 50; j += 32) {
        float a = b2s[j];
#pragma unroll 10
        for (int k = 0; k < 50; k++) a = fmaf(h1s[w][k], w2s[k * 50 + j], a);
        part += tanhf(a) * w3s[j];
    }
#pragma unroll
    for (int o = 16; o > 0; o >>= 1)
        part += __shfl_down_sync(0xffffffff, part, o);
    if (lane == 0) g_branch[w] = tanhf(part + b3s);
}

// ---------------- build lifting lookup table (8-way d-parallel) --------------
__global__ __launch_bounds__(512)
void k_tab(const float* __restrict__ l1w, const float* __restrict__ l1b,
           const float* __restrict__ l2w, const float* __restrict__ l2b) {
    __shared__ float s1w[256], s1b[256], s2w[256 * 12], s2b[12];
    __shared__ float red[7][64][12];
    int tid = threadIdx.x;
    if (tid < 256) { s1w[tid] = l1w[tid]; s1b[tid] = l1b[tid]; }
    for (int i = tid; i < 256 * 12; i += 512) s2w[i] = l2w[i];
    if (tid >= 256 && tid < 268) s2b[tid - 256] = l2b[tid - 256];
    __syncthreads();

    int pl = tid & 63, qd = tid >> 6;   // 64 points x 8 d-groups
    int pt = blockIdx.x * 64 + pl;
    float s = TAB_LO + (float)pt * TAB_STEP;
    float acc[12];
#pragma unroll
    for (int e = 0; e < 12; e++) acc[e] = 0.f;
    int d0 = qd * 32;
    for (int d = d0; d < d0 + 32; d++) {
        float u = fmaf(s, s1w[d], s1b[d]);
        float gl = gelu_exact(u);
#pragma unroll
        for (int e = 0; e < 12; e++) acc[e] = fmaf(gl, s2w[d * 12 + e], acc[e]);
    }
    if (qd > 0) {
#pragma unroll
        for (int e = 0; e < 12; e++) red[qd - 1][pl][e] = acc[e];
    }
    __syncthreads();
    if (qd == 0 && pt <= TAB_N) {
        float r[12];
#pragma unroll
        for (int e = 0; e < 12; e++) r[e] = acc[e] + s2b[e];
#pragma unroll
        for (int g = 0; g < 7; g++)
#pragma unroll
            for (int e = 0; e < 12; e++) r[e] += red[g][pl][e];
#pragma unroll
        for (int e = 0; e < 12; e++) g_tab[pt * 12 + e] = r[e];
    }
}

// ---------------- lifting via table interp ----------------------------------
__global__ void k_lift(const float* __restrict__ x) {
    int p = blockIdx.x * 256 + threadIdx.x;
    float s = x[p] * g_scale + g_shift;
    float f = (s - TAB_LO) * TAB_INV;
    f = fminf(fmaxf(f, 0.0f), (float)TAB_N - 0.0005f);
    int i0 = (int)f;
    float fr = f - (float)i0;
    const float* ta = g_tab + i0 * 12;
    int b = p >> 12, hw = p & 4095;
#pragma unroll
    for (int e = 0; e < 12; e++) {
        float a = ta[e], bb = ta[12 + e];
        g_t0[(b * HID + e) * HWSZ + hw] = fmaf(fr, bb - a, a);
    }
}

// ---------------- forward DFT (W then H) for layer 0, block per (b,c) -------
__global__ __launch_bounds__(512)
void k_fwd0() {
    __shared__ float ts[4096];
    __shared__ float2 xc[64 * 16];   // [h][k]
    __shared__ float2 tw[64];
    int tid = threadIdx.x;
    int bc = blockIdx.x;
    if (tid < 64) tw[tid] = g_tw[tid];
#pragma unroll
    for (int i = 0; i < 2; i++)
        *(float4*)&ts[(tid + i * 512) * 4] = *(const float4*)&g_t0[bc * HWSZ + (tid + i * 512) * 4];
    __syncthreads();

#pragma unroll
    for (int r = 0; r < 2; r++) {
        int o = tid + r * 512;
        int h = o >> 4, k = o & 15;
        float re = 0.f, im = 0.f;
#pragma unroll 8
        for (int w = 0; w < 64; w++) {
            float2 t = tw[(w * k) & 63];
            float v = ts[h * 64 + w];
            re = fmaf(v, t.x, re);
            im = fmaf(-v, t.y, im);
        }
        xc[h * 16 + k] = make_float2(re, im);
    }
    __syncthreads();

    int mi = tid >> 4, k = tid & 15;
    int m = mi + (mi >= 16 ? 32 : 0);
    float re = 0.f, im = 0.f;
#pragma unroll 8
    for (int h = 0; h < 64; h++) {
        float2 t = tw[(h * m) & 63];
        float2 v = xc[h * 16 + k];
        re += v.x * t.x + v.y * t.y;   // * e^{-i theta}
        im += v.y * t.x - v.x * t.y;
    }
    g_xftA[(bc * 32 + mi) * 16 + k] = make_float2(re, im);
}

// ---------------- fused layer: spec + invH + invW/skip/gelu + fwdW + fwdH ----
__global__ __launch_bounds__(512)
void k_layer(int lay,
             const float* __restrict__ sw1r, const float* __restrict__ sw1i,
             const float* __restrict__ sw2r, const float* __restrict__ sw2i,
             const float* __restrict__ skw_g, const float* __restrict__ skb_g) {
    const int in_flag = lay & 1;
    const float* tin = in_flag ? g_t1 : g_t0;
    float* tout = in_flag ? g_t0 : g_t1;
    const float2* xft_in = in_flag ? g_xftB : g_xftA;
    float2* xft_out = in_flag ? g_xftA : g_xftB;

    __shared__ float2 sy[32 * 16];     // spec output  [mi][k]
    __shared__ float2 Ys[64 * 16];     // invH output  [h][k]
    __shared__ float ts[4096];         // spatial field
    __shared__ float2 xc[64 * 16];     // fwdW output  [h][k]
    __shared__ float2 tw[64];
    __shared__ float skw[12];
    __shared__ float skb;

    int tid = threadIdx.x;
    int bo = blockIdx.x;
    int b = bo / 12, o = bo % 12;
    if (tid < 64) tw[tid] = g_tw[tid];
    if (tid >= 64 && tid < 76) skw[tid - 64] = skw_g[((lay * 12 + (tid - 64)) * 12) + o];
    if (tid == 76) skb = skb_g[lay * 12 + o];

    // ---- stage 1: spectral mix ----
    {
        int k = tid & 15, mi = tid >> 4;
        const float* wr = (mi < 16) ? sw1r : sw2r;
        const float* wi = (mi < 16) ? sw1i : sw2i;
        int mr = (mi < 16) ? mi : mi - 16;
        float yr = 0.f, yi = 0.f;
#pragma unroll
        for (int c = 0; c < 12; c++) {
            float2 xv = xft_in[((b * 12 + c) * 32 + mi) * 16 + k];
            int off = (((lay * 12 + c) * 12 + o) * 16 + mr) * 16 + k;
            float wre = wr[off], wim = wi[off];
            yr += xv.x * wre - xv.y * wim;
            yi += xv.x * wim + xv.y * wre;
        }
        sy[tid] = make_float2(yr, yi);
    }
    __syncthreads();

    // ---- stage 2: inverse H-DFT ----
#pragma unroll
    for (int r = 0; r < 2; r++) {
        int oo = tid + r * 512;
        int h = oo >> 4, k = oo & 15;
        float re = 0.f, im = 0.f;
#pragma unroll
        for (int mi = 0; mi < 32; mi++) {
            int m = mi + (mi >= 16 ? 32 : 0);
            float2 t = tw[(h * m) & 63];
            float2 v = sy[mi * 16 + k];
            re += v.x * t.x - v.y * t.y;   // * e^{+i theta}
            im += v.x * t.y + v.y * t.x;
        }
        Ys[h * 16 + k] = make_float2(re, im);
    }
    __syncthreads();

    // ---- stage 3: inverse W-DFT + skip conv (+ gelu) ----
    {
        int w = tid & 63, hg = tid >> 6;
#pragma unroll
        for (int i = 0; i < 8; i++) {
            int h = hg * 8 + i;
            const float2* yr = &Ys[h * 16];
            float v = yr[0].x;    // k=0: imaginary part discarded by irfft
#pragma unroll
            for (int k = 1; k < 16; k++) {
                float2 t = tw[(w * k) & 63];
                v += 2.f * (yr[k].x * t.x - yr[k].y * t.y);
            }
            v *= (1.0f / 4096.0f);
            float sk = skb;
#pragma unroll
            for (int c = 0; c < 12; c++)
                sk = fmaf(tin[(b * 12 + c) * HWSZ + h * 64 + w], skw[c], sk);
            float rres = v + sk;
            if (lay < 3) rres = gelu_tab(rres);
            ts[h * 64 + w] = rres;
            tout[(b * 12 + o) * HWSZ + h * 64 + w] = rres;
        }
    }
    if (lay == 3) return;
    __syncthreads();

    // ---- stage 4: forward W-DFT ----
#pragma unroll
    for (int r = 0; r < 2; r++) {
        int oo = tid + r * 512;
        int h = oo >> 4, k = oo & 15;
        float re = 0.f, im = 0.f;
#pragma unroll 8
        for (int w = 0; w < 64; w++) {
            float2 t = tw[(w * k) & 63];
            float v = ts[h * 64 + w];
            re = fmaf(v, t.x, re);
            im = fmaf(-v, t.y, im);
        }
        xc[h * 16 + k] = make_float2(re, im);
    }
    __syncthreads();

    // ---- stage 5: forward H-DFT ----
    {
        int mi = tid >> 4, k = tid & 15;
        int m = mi + (mi >= 16 ? 32 : 0);
        float re = 0.f, im = 0.f;
#pragma unroll 8
        for (int h = 0; h < 64; h++) {
            float2 t = tw[(h * m) & 63];
            float2 v = xc[h * 16 + k];
            re += v.x * t.x + v.y * t.y;   // * e^{-i theta}
            im += v.y * t.x - v.x * t.y;
        }
        xft_out[(bo * 32 + mi) * 16 + k] = make_float2(re, im);
    }
}

// ---------------- transpose + fp16-round p2w: [256][640] -> g_bt[640][256] ---
__global__ void k_transp(const float* __restrict__ w) {
    __shared__ float t[32][33];
    int e0 = blockIdx.x * 32, k0 = blockIdx.y * 32;
    t[threadIdx.y][threadIdx.x] = w[(k0 + threadIdx.y) * OUTC + e0 + threadIdx.x];
    __syncthreads();
    g_bt[(e0 + threadIdx.y) * 256 + k0 + threadIdx.x] = __float2half_rn(t[threadIdx.x][threadIdx.y]);
}

// ---------------- projection pass 1: 12 -> 256 gelu, q[p][k] fp16 ------------
__global__ void k_proj1(const float* __restrict__ p1w, const float* __restrict__ p1b) {
    __shared__ float w1s[12 * 256];
    __shared__ float b1s[256];
    int tid = threadIdx.x;
    int wid = tid >> 5, lid = tid & 31;
    if (tid < 256) b1s[tid] = p1b[tid];
    for (int i = tid; i < 12 * 256; i += 256) w1s[i] = p1w[i];
    __syncthreads();

    int p = blockIdx.x * 8 + wid;
    int b = p >> 12, hw = p & 4095;
    float tv[12];
#pragma unroll
    for (int c = 0; c < 12; c++) tv[c] = g_t0[(b * 12 + c) * HWSZ + hw];

#pragma unroll
    for (int r = 0; r < 2; r++) {
        int jb = r * 128 + lid * 4;
        float f[4];
#pragma unroll
        for (int jj = 0; jj < 4; jj++) {
            int j = jb + jj;
            float a = b1s[j];
#pragma unroll
            for (int c = 0; c < 12; c++) a = fmaf(tv[c], w1s[c * 256 + j], a);
            f[jj] = gelu_tab(a);
        }
        __half2 h01 = __floats2half2_rn(f[0], f[1]);
        __half2 h23 = __floats2half2_rn(f[2], f[3]);
        uint2 pk;
        pk.x = *(uint32_t*)&h01;
        pk.y = *(uint32_t*)&h23;
        *(uint2*)&g_q[(size_t)p * 256 + jb] = pk;
    }
}

// ---------------- projection pass 2: mma.sync fp16 GEMM 65536x640x256 --------
#define PADK 40        /* halves per smem row (80B), conflict-free */
#define STAGEH (2 * 128 * PADK)   /* halves per stage (A + B) */
#define NSTAGE 3

__device__ __forceinline__ void mma16n8k16(float* c, const uint32_t* a, const uint32_t* b) {
    asm volatile(
        "mma.sync.aligned.m16n8k16.row.col.f32.f16.f16.f32 "
        "{%0,%1,%2,%3}, {%4,%5,%6,%7}, {%8,%9}, {%0,%1,%2,%3};"
        : "+f"(c[0]), "+f"(c[1]), "+f"(c[2]), "+f"(c[3])
        : "r"(a[0]), "r"(a[1]), "r"(a[2]), "r"(a[3]), "r"(b[0]), "r"(b[1]));
}

__global__ __launch_bounds__(256, 2)
void k_gemm_mma(const float* __restrict__ p2b, float* __restrict__ out) {
    extern __shared__ __half smh[];
    __shared__ float sPb[128];
    int tid = threadIdx.x;
    int wid = tid >> 5, lane = tid & 31;
    int tig = lane & 3, grp = lane >> 2;
    int wm = wid & 1, wn = wid >> 1;         // warp tile: 64 rows x 32 cols
    int n0 = blockIdx.x * 128;
    int m0 = blockIdx.y * 128;
    if (tid < 128) sPb[tid] = p2b[n0 + tid];

    const __half* Aop = g_q + (size_t)m0 * 256;
    const __half* Bop = g_bt + (size_t)n0 * 256;

    float acc[4][4][4];
#pragma unroll
    for (int i = 0; i < 4; i++)
#pragma unroll
        for (int j = 0; j < 4; j++)
#pragma unroll
            for (int r = 0; r < 4; r++) acc[i][j][r] = 0.f;

// per chunk: A 128 rows x 32 halves (64B) + B same; 16B per cp.async
#define PREFETCH(ch) do {                                                     \
    int st_ = (ch) % NSTAGE;                                                  \
    __half* Ab_ = smh + st_ * STAGEH;                                         \
    __half* Bb_ = Ab_ + 128 * PADK;                                           \
    int k0_ = (ch) * 32;                                                      \
    _Pragma("unroll")                                                         \
    for (int it = 0; it < 2; it++) {                                          \
        int fi = tid + it * 256;              /* 0..511 */                    \
        int row = fi >> 2, c8 = (fi & 3) * 8;                                 \
        uint32_t da = (uint32_t)__cvta_generic_to_shared(Ab_ + row * PADK + c8); \
        const __half* ga = Aop + (size_t)row * 256 + k0_ + c8;                \
        asm volatile("cp.async.cg.shared.global [%0], [%1], 16;" :: "r"(da), "l"(ga)); \
        uint32_t db = (uint32_t)__cvta_generic_to_shared(Bb_ + row * PADK + c8); \
        const __half* gb = Bop + (size_t)row * 256 + k0_ + c8;                \
        asm volatile("cp.async.cg.shared.global [%0], [%1], 16;" :: "r"(db), "l"(gb)); \
    }                                                                         \
    asm volatile("cp.async.commit_group;" ::: "memory");                      \
} while (0)

    PREFETCH(0);
    PREFETCH(1);

    for (int ch = 0; ch < 8; ch++) {
        if (ch < 7) {
            asm volatile("cp.async.wait_group 1;" ::: "memory");
        } else {
            asm volatile("cp.async.wait_group 0;" ::: "memory");
        }
        __syncthreads();
        const __half* Ab = smh + (ch % NSTAGE) * STAGEH;
        const __half* Bb = Ab + 128 * PADK;

#pragma unroll
        for (int kk = 0; kk < 2; kk++) {      // two k16 steps per 32-chunk
            int kb = kk * 16;
            uint32_t af[4][4], bf[4][2];
#pragma unroll
            for (int mt = 0; mt < 4; mt++) {
                int r0 = wm * 64 + mt * 16 + grp;
                af[mt][0] = *(const uint32_t*)&Ab[r0 * PADK + kb + tig * 2];
                af[mt][1] = *(const uint32_t*)&Ab[(r0 + 8) * PADK + kb + tig * 2];
                af[mt][2] = *(const uint32_t*)&Ab[r0 * PADK + kb + tig * 2 + 8];
                af[mt][3] = *(const uint32_t*)&Ab[(r0 + 8) * PADK + kb + tig * 2 + 8];
            }
#pragma unroll
            for (int nt = 0; nt < 4; nt++) {
                int e = wn * 32 + nt * 8 + grp;
                bf[nt][0] = *(const uint32_t*)&Bb[e * PADK + kb + tig * 2];
                bf[nt][1] = *(const uint32_t*)&Bb[e * PADK + kb + tig * 2 + 8];
            }
#pragma unroll
            for (int mt = 0; mt < 4; mt++)
#pragma unroll
                for (int nt = 0; nt < 4; nt++)
                    mma16n8k16(acc[mt][nt], af[mt], bf[nt]);
        }
        if (ch + 2 < 8) PREFETCH(ch + 2);
    }

    // epilogue: (acc + bias) * branch
    float br = g_branch[m0 >> 12];
#pragma unroll
    for (int mt = 0; mt < 4; mt++) {
        int row0 = m0 + wm * 64 + mt * 16 + grp;
        int row1 = row0 + 8;
        float* o0 = out + (size_t)(row0 >> 6) * (OUTC * 64) + (row0 & 63);
        float* o1 = out + (size_t)(row1 >> 6) * (OUTC * 64) + (row1 & 63);
#pragma unroll
        for (int nt = 0; nt < 4; nt++) {
            int el = wn * 32 + nt * 8 + 2 * tig;     // local e in [0,128)
            int e = n0 + el;
            float b0 = sPb[el], b1 = sPb[el + 1];
            __stcs(o0 + (size_t)e * 64,       (acc[mt][nt][0] + b0) * br);
            __stcs(o0 + (size_t)(e + 1) * 64, (acc[mt][nt][1] + b1) * br);
            __stcs(o1 + (size_t)e * 64,       (acc[mt][nt][2] + b0) * br);
            __stcs(o1 + (size_t)(e + 1) * 64, (acc[mt][nt][3] + b1) * br);
        }
    }
#undef PREFETCH
}

#define GEMM_SMEM (NSTAGE * STAGEH * 2)   /* 61440 bytes */

// ---------------- launch ------------------------------------------------------
extern "C" void kernel_launch(void* const* d_in, const int* in_sizes, int n_in,
                              void* d_out, int out_size) {
    const float* x     = (const float*)d_in[0];
    const float* cond  = (const float*)d_in[1];
    const float* bn2_g = (const float*)d_in[2];
    const float* bn2_b = (const float*)d_in[3];
    const float* bn1_g = (const float*)d_in[4];
    const float* bn1_b = (const float*)d_in[5];
    const float* b_w1  = (const float*)d_in[6];
    const float* b_b1  = (const float*)d_in[7];
    const float* b_w2  = (const float*)d_in[8];
    const float* b_b2  = (const float*)d_in[9];
    const float* b_w3  = (const float*)d_in[10];
    const float* b_b3  = (const float*)d_in[11];
    const float* l1_w  = (const float*)d_in[12];
    const float* l1_b  = (const float*)d_in[13];
    const float* l2_w  = (const float*)d_in[14];
    const float* l2_b  = (const float*)d_in[15];
    const float* sw1r  = (const float*)d_in[16];
    const float* sw1i  = (const float*)d_in[17];
    const float* sw2r  = (const float*)d_in[18];
    const float* sw2i  = (const float*)d_in[19];
    const float* sk_w  = (const float*)d_in[20];
    const float* sk_b  = (const float*)d_in[21];
    const float* p1_w  = (const float*)d_in[22];
    const float* p1_b  = (const float*)d_in[23];
    const float* p2_w  = (const float*)d_in[24];
    const float* p2_b  = (const float*)d_in[25];
    float* out = (float*)d_out;

    cudaFuncSetAttribute(k_gemm_mma, cudaFuncAttributeMaxDynamicSharedMemorySize, GEMM_SMEM);

    k_setup<<<(GT_N + 256) / 256, 256>>>();
    k_stats<<<1, 1024>>>(x, bn2_g, bn2_b);
    k_branch<<<1, 512>>>(cond, bn1_g, bn1_b, b_w1, b_b1, b_w2, b_b2, b_w3, b_b3);
    k_tab<<<(TAB_N + 64) / 64, 512>>>(l1_w, l1_b, l2_w, l2_b);
    k_lift<<<NPIX / 256, 256>>>(x);

    dim3 tg(OUTC / 32, 256 / 32);
    k_transp<<<tg, dim3(32, 32)>>>(p2_w);

    k_fwd0<<<BB * HID, 512>>>();
    for (int lay = 0; lay < 4; lay++)
        k_layer<<<BB * HID, 512>>>(lay, sw1r, sw1i, sw2r, sw2i, sk_w, sk_b);

    k_proj1<<<NPIX / 8, 256>>>(p1_w, p1_b);

    dim3 gg(OUTC / 128, NPIX / 128);
    k_gemm_mma<<<gg, 256, GEMM_SMEM>>>(p2_b, out);
}

// round 9
// speedup vs baseline: 2.8143x; 1.0737x over previous
#include <cuda_runtime.h>
#include <cuda_fp16.h>
#include <math.h>
#include <stdint.h>

#define BB 16
#define HH 64
#define WW 64
#define HID 12
#define MODES 16
#define LIFTC 256
#define OUTC 640
#define NPIX (BB*HH*WW)      /* 65536 */
#define HWSZ (HH*WW)         /* 4096 */
#define EPS 1e-5f
#define TAB_N 8192
#define TAB_LO (-9.0f)
#define TAB_STEP (18.0f / TAB_N)
#define TAB_INV (TAB_N / 18.0f)
#define GT_N 8192            /* gelu table: [-8, 8], step 1/512 */

// ---------------- scratch (device globals; no allocations allowed) ----------
__device__ __align__(16) float2 g_tw[64];           // (cos, sin) interleaved
__device__ float g_scale, g_shift;
__device__ float g_branch[BB];
__device__ __align__(16) float g_t0[BB*HID*HWSZ];   // 3 MB ping
__device__ __align__(16) float g_t1[BB*HID*HWSZ];   // 3 MB pong
__device__ __align__(16) float2 g_xftA[BB*HID*32*MODES];  // spectrum ping
__device__ __align__(16) float2 g_xftB[BB*HID*32*MODES];  // spectrum pong
__device__ __align__(16) __half g_q[NPIX*LIFTC];          // 32 MB, [p][k], fp16
__device__ __align__(16) __half g_bt[OUTC*LIFTC];         // 320 KB, [e][k], fp16
__device__ __align__(16) float g_tab[12 * (TAB_N + 1)];   // lifting table, CHANNEL-major
__device__ __align__(16) float g_gt[GT_N + 1];            // gelu lookup table

__device__ __forceinline__ float gelu_exact(float x) { return x * normcdff(x); }

// table gelu: linear interp on [-8,8], exact tails
__device__ __forceinline__ float gelu_tab(float a) {
    float f = fmaf(a, 512.0f, 4096.0f);
    f = fminf(fmaxf(f, 0.0f), 8191.999f);
    int i = (int)f;
    float fr = f - (float)i;
    float a0 = g_gt[i], a1 = g_gt[i + 1];
    float g = fmaf(fr, a1 - a0, a0);
    return (a >= 8.0f) ? a : g;
}

// ---------------- combined prologue ------------------------------------------
// blocks [0,129): lifting table   [129,289): transpose p2w
// [289,306): gelu table (+tw in 289)   306: bn stats   307: branch MLP
#define PRO_TAB0 0
#define PRO_TRA0 129
#define PRO_SET0 289
#define PRO_STAT 306
#define PRO_BRAN 307
#define PRO_GRID 308

__global__ __launch_bounds__(512)
void k_prolog(const float* __restrict__ x,
              const float* __restrict__ bn2_g, const float* __restrict__ bn2_b,
              const float* __restrict__ cond,
              const float* __restrict__ g1, const float* __restrict__ b1,
              const float* __restrict__ w1, const float* __restrict__ bb1,
              const float* __restrict__ w2, const float* __restrict__ bb2,
              const float* __restrict__ w3, const float* __restrict__ bb3,
              const float* __restrict__ l1w, const float* __restrict__ l1b,
              const float* __restrict__ l2w, const float* __restrict__ l2b,
              const float* __restrict__ p2w) {
    __shared__ __align__(16) char shm[36864];
    int tid = threadIdx.x;
    int blk = blockIdx.x;

    if (blk < PRO_TRA0) {
        // ---- lifting table, 64 points x 8 d-groups ----
        float* s1w = (float*)shm;            // 256
        float* s1b = s1w + 256;              // 256
        float* s2w = s1b + 256;              // 3072
        float* s2b = s2w + 3072;             // 12 (+4 pad)
        float* red = s2b + 16;               // 7*64*12 = 5376
        if (tid < 256) { s1w[tid] = l1w[tid]; s1b[tid] = l1b[tid]; }
        for (int i = tid; i < 256 * 12; i += 512) s2w[i] = l2w[i];
        if (tid >= 256 && tid < 268) s2b[tid - 256] = l2b[tid - 256];
        __syncthreads();

        int pl = tid & 63, qd = tid >> 6;
        int pt = blk * 64 + pl;
        float s = TAB_LO + (float)pt * TAB_STEP;
        float acc[12];
#pragma unroll
        for (int e = 0; e < 12; e++) acc[e] = 0.f;
        int d0 = qd * 32;
        for (int d = d0; d < d0 + 32; d++) {
            float u = fmaf(s, s1w[d], s1b[d]);
            float gl = gelu_exact(u);
#pragma unroll
            for (int e = 0; e < 12; e++) acc[e] = fmaf(gl, s2w[d * 12 + e], acc[e]);
        }
        if (qd > 0) {
#pragma unroll
            for (int e = 0; e < 12; e++) red[((qd - 1) * 64 + pl) * 12 + e] = acc[e];
        }
        __syncthreads();
        if (qd == 0 && pt <= TAB_N) {
            float r[12];
#pragma unroll
            for (int e = 0; e < 12; e++) r[e] = acc[e] + s2b[e];
#pragma unroll
            for (int g = 0; g < 7; g++)
#pragma unroll
                for (int e = 0; e < 12; e++) r[e] += red[(g * 64 + pl) * 12 + e];
#pragma unroll
            for (int e = 0; e < 12; e++) g_tab[e * (TAB_N + 1) + pt] = r[e];
        }
    } else if (blk < PRO_SET0) {
        // ---- transpose + fp16 p2w: [256][640] -> g_bt[640][256] ----
        float (*t)[33] = (float(*)[33])shm;
        int bx = blk - PRO_TRA0;
        int e0 = (bx % 20) * 32, k0 = (bx / 20) * 32;
        int tx = tid & 31, ty = tid >> 5;    // 32 x 16
#pragma unroll
        for (int r = 0; r < 2; r++)
            t[ty + r * 16][tx] = p2w[(k0 + ty + r * 16) * OUTC + e0 + tx];
        __syncthreads();
#pragma unroll
        for (int r = 0; r < 2; r++)
            g_bt[(e0 + ty + r * 16) * 256 + k0 + tx] = __float2half_rn(t[tx][ty + r * 16]);
    } else if (blk < PRO_STAT) {
        // ---- gelu table (+ twiddles in first block) ----
        int sb = blk - PRO_SET0;
        if (sb == 0 && tid < 64) {
            float s, c;
            sincospif((float)tid / 32.0f, &s, &c);
            g_tw[tid] = make_float2(c, s);
        }
        int idx = sb * 512 + tid;
        if (idx <= GT_N) {
            float xx = -8.0f + (float)idx * (16.0f / GT_N);
            g_gt[idx] = gelu_exact(xx);
        }
    } else if (blk == PRO_STAT) {
        // ---- batchnorm2d stats ----
        double* ssum = (double*)shm;         // 512
        double* ssq = ssum + 512;            // 512
        double s = 0.0, q = 0.0;
        const float4* x4 = (const float4*)x;
        for (int i = tid; i < NPIX / 4; i += 512) {
            float4 v = x4[i];
            s += (double)v.x + (double)v.y + (double)v.z + (double)v.w;
            q += (double)v.x * v.x + (double)v.y * v.y + (double)v.z * v.z + (double)v.w * v.w;
        }
        ssum[tid] = s; ssq[tid] = q;
        __syncthreads();
        for (int o = 256; o > 0; o >>= 1) {
            if (tid < o) { ssum[tid] += ssum[tid + o]; ssq[tid] += ssq[tid + o]; }
            __syncthreads();
        }
        if (tid == 0) {
            double m = ssum[0] / (double)NPIX;
            double var = ssq[0] / (double)NPIX - m * m;
            float rstd = rsqrtf((float)var + EPS);
            float sc = bn2_g[0] * rstd;
            g_scale = sc;
            g_shift = bn2_b[0] - (float)m * sc;
        }
    } else {
        // ---- condition BN + branch MLP (warp per sample) ----
        float* w1s = (float*)shm;            // 100
        float* b1s = w1s + 104;              // 50
        float* w2s = b1s + 56;               // 2500
        float* b2s = w2s + 2500;             // 50
        float* w3s = b2s + 52;               // 50
        float* b3s = w3s + 52;               // 1
        float* cs  = b3s + 3;                // 2
        float* cb  = cs + 2;                 // 2
        float* h1s = cb + 2;                 // 16*52
        int w = tid >> 5, lane = tid & 31;

        if (tid < 100) w1s[tid] = w1[tid];
        if (tid >= 128 && tid < 178) b1s[tid - 128] = bb1[tid - 128];
        if (tid >= 192 && tid < 242) b2s[tid - 192] = bb2[tid - 192];
        if (tid >= 256 && tid < 306) w3s[tid - 256] = w3[tid - 256];
        if (tid == 320) b3s[0] = bb3[0];
        for (int i = tid; i < 2500; i += 512) w2s[i] = w2[i];
        if (tid < 2) {
            float m = 0.f;
            for (int b = 0; b < BB; b++) m += cond[b * 2 + tid];
            m /= (float)BB;
            float v = 0.f;
            for (int b = 0; b < BB; b++) { float d = cond[b * 2 + tid] - m; v += d * d; }
            v /= (float)BB;
            float sc = rsqrtf(v + EPS) * g1[tid];
            cs[tid] = sc;
            cb[tid] = b1[tid] - m * sc;
        }
        __syncthreads();

        float c0 = cond[w * 2 + 0] * cs[0] + cb[0];
        float c1 = cond[w * 2 + 1] * cs[1] + cb[1];
        for (int j = lane; j < 50; j += 32)
            h1s[w * 52 + j] = tanhf(c0 * w1s[j] + c1 * w1s[50 + j] + b1s[j]);
        __syncwarp();

        float part = 0.f;
        for (int j = lane; j < 50; j += 32) {
            float a = b2s[j];
#pragma unroll 10
            for (int k = 0; k < 50; k++) a = fmaf(h1s[w * 52 + k], w2s[k * 50 + j], a);
            part += tanhf(a) * w3s[j];
        }
#pragma unroll
        for (int o = 16; o > 0; o >>= 1)
            part += __shfl_down_sync(0xffffffff, part, o);
        if (lane == 0) g_branch[w] = tanhf(part + b3s[0]);
    }
}

// ---------------- fused lift + forward DFT, block per (b,c) ------------------
__global__ __launch_bounds__(512)
void k_fwd0l(const float* __restrict__ x) {
    __shared__ float ts[4096];
    __shared__ float2 xc[64 * 16];   // [h][k]
    __shared__ float2 tw[64];
    int tid = threadIdx.x;
    int bc = blockIdx.x;
    int b = bc / 12, c = bc % 12;
    if (tid < 64) tw[tid] = g_tw[tid];

    // lift: table interp for channel c, 8 px per thread
    const float* tabc = g_tab + c * (TAB_N + 1);
    float sc = g_scale, sh = g_shift;
#pragma unroll
    for (int i = 0; i < 8; i++) {
        int p = tid + i * 512;
        float s = fmaf(x[b * HWSZ + p], sc, sh);
        float f = (s - TAB_LO) * TAB_INV;
        f = fminf(fmaxf(f, 0.0f), (float)TAB_N - 0.0005f);
        int i0 = (int)f;
        float fr = f - (float)i0;
        float a = tabc[i0], bb2 = tabc[i0 + 1];
        float v = fmaf(fr, bb2 - a, a);
        ts[p] = v;
        g_t0[bc * HWSZ + p] = v;
    }
    __syncthreads();

    // forward W-DFT
#pragma unroll
    for (int r = 0; r < 2; r++) {
        int o = tid + r * 512;
        int h = o >> 4, k = o & 15;
        float re = 0.f, im = 0.f;
#pragma unroll 8
        for (int w = 0; w < 64; w++) {
            float2 t = tw[(w * k) & 63];
            float v = ts[h * 64 + w];
            re = fmaf(v, t.x, re);
            im = fmaf(-v, t.y, im);
        }
        xc[h * 16 + k] = make_float2(re, im);
    }
    __syncthreads();

    // forward H-DFT at 32 mode rows
    int mi = tid >> 4, k = tid & 15;
    int m = mi + (mi >= 16 ? 32 : 0);
    float re = 0.f, im = 0.f;
#pragma unroll 8
    for (int h = 0; h < 64; h++) {
        float2 t = tw[(h * m) & 63];
        float2 v = xc[h * 16 + k];
        re += v.x * t.x + v.y * t.y;   // * e^{-i theta}
        im += v.y * t.x - v.x * t.y;
    }
    g_xftA[(bc * 32 + mi) * 16 + k] = make_float2(re, im);
}

// ---------------- fused layer: spec + invH + invW/skip/gelu + fwdW + fwdH ----
__global__ __launch_bounds__(512)
void k_layer(int lay,
             const float* __restrict__ sw1r, const float* __restrict__ sw1i,
             const float* __restrict__ sw2r, const float* __restrict__ sw2i,
             const float* __restrict__ skw_g, const float* __restrict__ skb_g) {
    const int in_flag = lay & 1;
    const float* tin = in_flag ? g_t1 : g_t0;
    float* tout = in_flag ? g_t0 : g_t1;
    const float2* xft_in = in_flag ? g_xftB : g_xftA;
    float2* xft_out = in_flag ? g_xftA : g_xftB;

    __shared__ float2 sy[32 * 16];     // spec output  [mi][k]
    __shared__ float2 Ys[64 * 16];     // invH output  [h][k]
    __shared__ float ts[4096];         // spatial field
    __shared__ float2 xc[64 * 16];     // fwdW output  [h][k]
    __shared__ float2 tw[64];
    __shared__ float skw[12];
    __shared__ float skb;

    int tid = threadIdx.x;
    int bo = blockIdx.x;
    int b = bo / 12, o = bo % 12;
    if (tid < 64) tw[tid] = g_tw[tid];
    if (tid >= 64 && tid < 76) skw[tid - 64] = skw_g[((lay * 12 + (tid - 64)) * 12) + o];
    if (tid == 76) skb = skb_g[lay * 12 + o];

    // ---- stage 1: spectral mix ----
    {
        int k = tid & 15, mi = tid >> 4;
        const float* wr = (mi < 16) ? sw1r : sw2r;
        const float* wi = (mi < 16) ? sw1i : sw2i;
        int mr = (mi < 16) ? mi : mi - 16;
        float yr = 0.f, yi = 0.f;
#pragma unroll
        for (int c = 0; c < 12; c++) {
            float2 xv = xft_in[((b * 12 + c) * 32 + mi) * 16 + k];
            int off = (((lay * 12 + c) * 12 + o) * 16 + mr) * 16 + k;
            float wre = wr[off], wim = wi[off];
            yr += xv.x * wre - xv.y * wim;
            yi += xv.x * wim + xv.y * wre;
        }
        sy[tid] = make_float2(yr, yi);
    }
    __syncthreads();

    // ---- stage 2: inverse H-DFT ----
#pragma unroll
    for (int r = 0; r < 2; r++) {
        int oo = tid + r * 512;
        int h = oo >> 4, k = oo & 15;
        float re = 0.f, im = 0.f;
#pragma unroll
        for (int mi = 0; mi < 32; mi++) {
            int m = mi + (mi >= 16 ? 32 : 0);
            float2 t = tw[(h * m) & 63];
            float2 v = sy[mi * 16 + k];
            re += v.x * t.x - v.y * t.y;   // * e^{+i theta}
            im += v.x * t.y + v.y * t.x;
        }
        Ys[h * 16 + k] = make_float2(re, im);
    }
    __syncthreads();

    // ---- stage 3: inverse W-DFT + skip conv (+ gelu) ----
    {
        int w = tid & 63, hg = tid >> 6;
#pragma unroll
        for (int i = 0; i < 8; i++) {
            int h = hg * 8 + i;
            const float2* yr = &Ys[h * 16];
            float v = yr[0].x;    // k=0: imaginary part discarded by irfft
#pragma unroll
            for (int k = 1; k < 16; k++) {
                float2 t = tw[(w * k) & 63];
                v += 2.f * (yr[k].x * t.x - yr[k].y * t.y);
            }
            v *= (1.0f / 4096.0f);
            float sk = skb;
#pragma unroll
            for (int c = 0; c < 12; c++)
                sk = fmaf(tin[(b * 12 + c) * HWSZ + h * 64 + w], skw[c], sk);
            float rres = v + sk;
            if (lay < 3) rres = gelu_tab(rres);
            ts[h * 64 + w] = rres;
            tout[(b * 12 + o) * HWSZ + h * 64 + w] = rres;
        }
    }
    if (lay == 3) return;
    __syncthreads();

    // ---- stage 4: forward W-DFT ----
#pragma unroll
    for (int r = 0; r < 2; r++) {
        int oo = tid + r * 512;
        int h = oo >> 4, k = oo & 15;
        float re = 0.f, im = 0.f;
#pragma unroll 8
        for (int w = 0; w < 64; w++) {
            float2 t = tw[(w * k) & 63];
            float v = ts[h * 64 + w];
            re = fmaf(v, t.x, re);
            im = fmaf(-v, t.y, im);
        }
        xc[h * 16 + k] = make_float2(re, im);
    }
    __syncthreads();

    // ---- stage 5: forward H-DFT ----
    {
        int mi = tid >> 4, k = tid & 15;
        int m = mi + (mi >= 16 ? 32 : 0);
        float re = 0.f, im = 0.f;
#pragma unroll 8
        for (int h = 0; h < 64; h++) {
            float2 t = tw[(h * m) & 63];
            float2 v = xc[h * 16 + k];
            re += v.x * t.x + v.y * t.y;   // * e^{-i theta}
            im += v.y * t.x - v.x * t.y;
        }
        xft_out[(bo * 32 + mi) * 16 + k] = make_float2(re, im);
    }
}

// ---------------- projection pass 1: 12 -> 256 gelu, q[p][k] fp16 ------------
__global__ void k_proj1(const float* __restrict__ p1w, const float* __restrict__ p1b) {
    __shared__ float w1s[12 * 256];
    __shared__ float b1s[256];
    int tid = threadIdx.x;
    int wid = tid >> 5, lid = tid & 31;
    if (tid < 256) b1s[tid] = p1b[tid];
    for (int i = tid; i < 12 * 256; i += 256) w1s[i] = p1w[i];
    __syncthreads();

    int p = blockIdx.x * 8 + wid;
    int b = p >> 12, hw = p & 4095;
    float tv[12];
#pragma unroll
    for (int c = 0; c < 12; c++) tv[c] = g_t0[(b * 12 + c) * HWSZ + hw];

#pragma unroll
    for (int r = 0; r < 2; r++) {
        int jb = r * 128 + lid * 4;
        float f[4];
#pragma unroll
        for (int jj = 0; jj < 4; jj++) {
            int j = jb + jj;
            float a = b1s[j];
#pragma unroll
            for (int c = 0; c < 12; c++) a = fmaf(tv[c], w1s[c * 256 + j], a);
            f[jj] = gelu_tab(a);
        }
        __half2 h01 = __floats2half2_rn(f[0], f[1]);
        __half2 h23 = __floats2half2_rn(f[2], f[3]);
        uint2 pk;
        pk.x = *(uint32_t*)&h01;
        pk.y = *(uint32_t*)&h23;
        *(uint2*)&g_q[(size_t)p * 256 + jb] = pk;
    }
}

// ---------------- projection pass 2: mma.sync fp16 GEMM 65536x640x256 --------
#define PADK 40        /* halves per smem row (80B), conflict-free */
#define STAGEH (2 * 128 * PADK)   /* halves per stage (A + B) */
#define NSTAGE 3

__device__ __forceinline__ void mma16n8k16(float* c, const uint32_t* a, const uint32_t* b) {
    asm volatile(
        "mma.sync.aligned.m16n8k16.row.col.f32.f16.f16.f32 "
        "{%0,%1,%2,%3}, {%4,%5,%6,%7}, {%8,%9}, {%0,%1,%2,%3};"
        : "+f"(c[0]), "+f"(c[1]), "+f"(c[2]), "+f"(c[3])
        : "r"(a[0]), "r"(a[1]), "r"(a[2]), "r"(a[3]), "r"(b[0]), "r"(b[1]));
}

__global__ __launch_bounds__(256, 2)
void k_gemm_mma(const float* __restrict__ p2b, float* __restrict__ out) {
    extern __shared__ __half smh[];
    __shared__ float sPb[128];
    int tid = threadIdx.x;
    int wid = tid >> 5, lane = tid & 31;
    int tig = lane & 3, grp = lane >> 2;
    int wm = wid & 1, wn = wid >> 1;         // warp tile: 64 rows x 32 cols
    int n0 = blockIdx.x * 128;
    int m0 = blockIdx.y * 128;
    if (tid < 128) sPb[tid] = p2b[n0 + tid];

    const __half* Aop = g_q + (size_t)m0 * 256;
    const __half* Bop = g_bt + (size_t)n0 * 256;

    float acc[4][4][4];
#pragma unroll
    for (int i = 0; i < 4; i++)
#pragma unroll
        for (int j = 0; j < 4; j++)
#pragma unroll
            for (int r = 0; r < 4; r++) acc[i][j][r] = 0.f;

#define PREFETCH(ch) do {                                                     \
    int st_ = (ch) % NSTAGE;                                                  \
    __half* Ab_ = smh + st_ * STAGEH;                                         \
    __half* Bb_ = Ab_ + 128 * PADK;                                           \
    int k0_ = (ch) * 32;                                                      \
    _Pragma("unroll")                                                         \
    for (int it = 0; it < 2; it++) {                                          \
        int fi = tid + it * 256;              /* 0..511 */                    \
        int row = fi >> 2, c8 = (fi & 3) * 8;                                 \
        uint32_t da = (uint32_t)__cvta_generic_to_shared(Ab_ + row * PADK + c8); \
        const __half* ga = Aop + (size_t)row * 256 + k0_ + c8;                \
        asm volatile("cp.async.cg.shared.global [%0], [%1], 16;" :: "r"(da), "l"(ga)); \
        uint32_t db = (uint32_t)__cvta_generic_to_shared(Bb_ + row * PADK + c8); \
        const __half* gb = Bop + (size_t)row * 256 + k0_ + c8;                \
        asm volatile("cp.async.cg.shared.global [%0], [%1], 16;" :: "r"(db), "l"(gb)); \
    }                                                                         \
    asm volatile("cp.async.commit_group;" ::: "memory");                      \
} while (0)

    PREFETCH(0);
    PREFETCH(1);

    for (int ch = 0; ch < 8; ch++) {
        if (ch < 7) {
            asm volatile("cp.async.wait_group 1;" ::: "memory");
        } else {
            asm volatile("cp.async.wait_group 0;" ::: "memory");
        }
        __syncthreads();
        const __half* Ab = smh + (ch % NSTAGE) * STAGEH;
        const __half* Bb = Ab + 128 * PADK;

#pragma unroll
        for (int kk = 0; kk < 2; kk++) {      // two k16 steps per 32-chunk
            int kb = kk * 16;
            uint32_t af[4][4], bf[4][2];
#pragma unroll
            for (int mt = 0; mt < 4; mt++) {
                int r0 = wm * 64 + mt * 16 + grp;
                af[mt][0] = *(const uint32_t*)&Ab[r0 * PADK + kb + tig * 2];
                af[mt][1] = *(const uint32_t*)&Ab[(r0 + 8) * PADK + kb + tig * 2];
                af[mt][2] = *(const uint32_t*)&Ab[r0 * PADK + kb + tig * 2 + 8];
                af[mt][3] = *(const uint32_t*)&Ab[(r0 + 8) * PADK + kb + tig * 2 + 8];
            }
#pragma unroll
            for (int nt = 0; nt < 4; nt++) {
                int e = wn * 32 + nt * 8 + grp;
                bf[nt][0] = *(const uint32_t*)&Bb[e * PADK + kb + tig * 2];
                bf[nt][1] = *(const uint32_t*)&Bb[e * PADK + kb + tig * 2 + 8];
            }
#pragma unroll
            for (int mt = 0; mt < 4; mt++)
#pragma unroll
                for (int nt = 0; nt < 4; nt++)
                    mma16n8k16(acc[mt][nt], af[mt], bf[nt]);
        }
        if (ch + 2 < 8) PREFETCH(ch + 2);
    }

    // epilogue: (acc + bias) * branch
    float br = g_branch[m0 >> 12];
#pragma unroll
    for (int mt = 0; mt < 4; mt++) {
        int row0 = m0 + wm * 64 + mt * 16 + grp;
        int row1 = row0 + 8;
        float* o0 = out + (size_t)(row0 >> 6) * (OUTC * 64) + (row0 & 63);
        float* o1 = out + (size_t)(row1 >> 6) * (OUTC * 64) + (row1 & 63);
#pragma unroll
        for (int nt = 0; nt < 4; nt++) {
            int el = wn * 32 + nt * 8 + 2 * tig;     // local e in [0,128)
            int e = n0 + el;
            float b0 = sPb[el], b1 = sPb[el + 1];
            __stcs(o0 + (size_t)e * 64,       (acc[mt][nt][0] + b0) * br);
            __stcs(o0 + (size_t)(e + 1) * 64, (acc[mt][nt][1] + b1) * br);
            __stcs(o1 + (size_t)e * 64,       (acc[mt][nt][2] + b0) * br);
            __stcs(o1 + (size_t)(e + 1) * 64, (acc[mt][nt][3] + b1) * br);
        }
    }
#undef PREFETCH
}

#define GEMM_SMEM (NSTAGE * STAGEH * 2)   /* 61440 bytes */

// ---------------- launch ------------------------------------------------------
extern "C" void kernel_launch(void* const* d_in, const int* in_sizes, int n_in,
                              void* d_out, int out_size) {
    const float* x     = (const float*)d_in[0];
    const float* cond  = (const float*)d_in[1];
    const float* bn2_g = (const float*)d_in[2];
    const float* bn2_b = (const float*)d_in[3];
    const float* bn1_g = (const float*)d_in[4];
    const float* bn1_b = (const float*)d_in[5];
    const float* b_w1  = (const float*)d_in[6];
    const float* b_b1  = (const float*)d_in[7];
    const float* b_w2  = (const float*)d_in[8];
    const float* b_b2  = (const float*)d_in[9];
    const float* b_w3  = (const float*)d_in[10];
    const float* b_b3  = (const float*)d_in[11];
    const float* l1_w  = (const float*)d_in[12];
    const float* l1_b  = (const float*)d_in[13];
    const float* l2_w  = (const float*)d_in[14];
    const float* l2_b  = (const float*)d_in[15];
    const float* sw1r  = (const float*)d_in[16];
    const float* sw1i  = (const float*)d_in[17];
    const float* sw2r  = (const float*)d_in[18];
    const float* sw2i  = (const float*)d_in[19];
    const float* sk_w  = (const float*)d_in[20];
    const float* sk_b  = (const float*)d_in[21];
    const float* p1_w  = (const float*)d_in[22];
    const float* p1_b  = (const float*)d_in[23];
    const float* p2_w  = (const float*)d_in[24];
    const float* p2_b  = (const float*)d_in[25];
    float* out = (float*)d_out;

    cudaFuncSetAttribute(k_gemm_mma, cudaFuncAttributeMaxDynamicSharedMemorySize, GEMM_SMEM);

    k_prolog<<<PRO_GRID, 512>>>(x, bn2_g, bn2_b, cond, bn1_g, bn1_b,
                                b_w1, b_b1, b_w2, b_b2, b_w3, b_b3,
                                l1_w, l1_b, l2_w, l2_b, p2_w);

    k_fwd0l<<<BB * HID, 512>>>(x);
    for (int lay = 0; lay < 4; lay++)
        k_layer<<<BB * HID, 512>>>(lay, sw1r, sw1i, sw2r, sw2i, sk_w, sk_b);

    k_proj1<<<NPIX / 8, 256>>>(p1_w, p1_b);

    dim3 gg(OUTC / 128, NPIX / 128);
    k_gemm_mma<<<gg, 256, GEMM_SMEM>>>(p2_b, out);
}